// round 1
// baseline (speedup 1.0000x reference)
#include <cuda_runtime.h>
#include <math.h>

// Problem constants
#define Bc 128
#define Pc 196
#define Dc 2048
#define Ac 512
#define Ec 512
#define Hc 512
#define Vc 10000
#define Tc 19
#define TMAXc 20

// ---------------- scratch (device globals; no allocation allowed) ----------
__device__ float g_meanf[Bc * Dc];
__device__ float g_h[Bc * Hc];
__device__ float g_c[Bc * Hc];
__device__ float g_hn[Bc * Hc];
__device__ float g_att1[(size_t)Bc * Pc * Ac];     // 25088 x 512
__device__ float g_eseq[(size_t)Bc * Tc * Ec];
__device__ float g_att2[Bc * Ac];
__device__ float g_alpha[Bc * Pc];                 // holds e, then alpha (in place)
__device__ float g_awe[Bc * Dc];
__device__ float g_gate[Bc * Dc];
__device__ float g_xin[Bc * (Ec + Dc)];
__device__ float g_gates[Bc * 4 * Hc];

// ---------------- kernels --------------------------------------------------

__global__ void mean_kernel(const float* __restrict__ f) {
    int idx = blockIdx.x * blockDim.x + threadIdx.x;
    if (idx >= Bc * Dc) return;
    int b = idx / Dc, d = idx % Dc;
    const float* p = f + (size_t)b * Pc * Dc + d;
    float s = 0.f;
    #pragma unroll 4
    for (int i = 0; i < Pc; i++) s += p[(size_t)i * Dc];
    g_meanf[idx] = s * (1.0f / Pc);
}

__global__ void embed_kernel(const float* __restrict__ emb, const int* __restrict__ cap) {
    int idx = blockIdx.x * blockDim.x + threadIdx.x;
    if (idx >= Bc * Tc * Ec) return;
    int j = idx % Ec;
    int bt = idx / Ec;
    int t = bt % Tc;
    int b = bt / Tc;
    int tok = cap[b * TMAXc + t];
    g_eseq[idx] = emb[(size_t)tok * Ec + j];
}

// Generic tiled fp32 GEMM: C[M,N] = act(A[M,K] @ W[K,N] + bias (+ C if accum)) * rowmask
// K must be a multiple of 8 (all our K: 512, 2048, 2560).
#define BM 64
#define BN 64
#define BK 8
__global__ void __launch_bounds__(256) gemm_kernel(
    const float* __restrict__ A, const float* __restrict__ W,
    const float* __restrict__ bias, float* __restrict__ C,
    int M, int N, int K, int ldc, int accum, int act,
    const int* __restrict__ lengths, int t)
{
    __shared__ float As[BK][BM];
    __shared__ float Ws[BK][BN];
    int tid = threadIdx.x;
    int tx = tid & 15, ty = tid >> 4;
    int row0 = blockIdx.y * BM, col0 = blockIdx.x * BN;
    float acc[4][4] = {};
    for (int k0 = 0; k0 < K; k0 += BK) {
        int i = tid;
        #pragma unroll
        for (int l = 0; l < 2; l++, i += 256) {    // 512 A elems
            int r = i >> 3, kk = i & 7;
            int gr = row0 + r;
            As[kk][r] = (gr < M) ? A[(size_t)gr * K + k0 + kk] : 0.f;
        }
        i = tid;
        #pragma unroll
        for (int l = 0; l < 2; l++, i += 256) {    // 512 W elems
            int kk = i >> 6, cc = i & 63;
            int gc = col0 + cc;
            Ws[kk][cc] = (gc < N) ? W[(size_t)(k0 + kk) * N + gc] : 0.f;
        }
        __syncthreads();
        #pragma unroll
        for (int kk = 0; kk < BK; kk++) {
            float4 av = *reinterpret_cast<const float4*>(&As[kk][ty * 4]);
            float4 wv = *reinterpret_cast<const float4*>(&Ws[kk][tx * 4]);
            float a4[4] = {av.x, av.y, av.z, av.w};
            float w4[4] = {wv.x, wv.y, wv.z, wv.w};
            #pragma unroll
            for (int ii = 0; ii < 4; ii++)
                #pragma unroll
                for (int jj = 0; jj < 4; jj++)
                    acc[ii][jj] = fmaf(a4[ii], w4[jj], acc[ii][jj]);
        }
        __syncthreads();
    }
    #pragma unroll
    for (int ii = 0; ii < 4; ii++) {
        int r = row0 + ty * 4 + ii;
        if (r >= M) continue;
        float mf = 1.f;
        if (lengths) mf = (t < lengths[r] - 1) ? 1.f : 0.f;
        #pragma unroll
        for (int jj = 0; jj < 4; jj++) {
            int cidx = col0 + tx * 4 + jj;
            if (cidx >= N) continue;
            float v = acc[ii][jj] + (bias ? bias[cidx] : 0.f);
            if (accum) v += C[(size_t)r * ldc + cidx];
            if (act == 1) v = 1.f / (1.f + expf(-v));
            v *= mf;
            C[(size_t)r * ldc + cidx] = v;
        }
    }
}

// e[b,p] = sum_a relu(att1[b,p,a] + att2[b,a]) * att_w[a] + att_b
// grid: (ceil(P/4), B), 128 threads; one warp per p.
__global__ void att_score_kernel(const float* __restrict__ att_w, const float* __restrict__ att_b) {
    __shared__ float s2[Ac];
    __shared__ float sw[Ac];
    int b = blockIdx.y;
    int tid = threadIdx.x;
    for (int i = tid; i < Ac; i += 128) {
        s2[i] = g_att2[b * Ac + i];
        sw[i] = att_w[i];
    }
    __syncthreads();
    int warp = tid >> 5, lane = tid & 31;
    int p = blockIdx.x * 4 + warp;
    if (p < Pc) {
        const float* a1 = g_att1 + ((size_t)b * Pc + p) * Ac;
        float s = 0.f;
        #pragma unroll 4
        for (int a = lane; a < Ac; a += 32) {
            float v = a1[a] + s2[a];
            v = fmaxf(v, 0.f);
            s += v * sw[a];
        }
        #pragma unroll
        for (int o = 16; o > 0; o >>= 1) s += __shfl_xor_sync(0xffffffffu, s, o);
        if (lane == 0) g_alpha[b * Pc + p] = s + att_b[0];
    }
}

// softmax over P per batch row; writes alpha in place + masked alphas to output
__global__ void softmax_kernel(const int* __restrict__ lengths, int t, float* __restrict__ out_alphas) {
    int b = blockIdx.x;
    int tid = threadIdx.x;  // 256
    __shared__ float red[256];
    float v = (tid < Pc) ? g_alpha[b * Pc + tid] : -1e30f;
    red[tid] = v;
    __syncthreads();
    for (int s = 128; s > 0; s >>= 1) {
        if (tid < s) red[tid] = fmaxf(red[tid], red[tid + s]);
        __syncthreads();
    }
    float mx = red[0];
    __syncthreads();
    float ex = (tid < Pc) ? expf(v - mx) : 0.f;
    red[tid] = ex;
    __syncthreads();
    for (int s = 128; s > 0; s >>= 1) {
        if (tid < s) red[tid] += red[tid + s];
        __syncthreads();
    }
    float inv = 1.0f / red[0];
    if (tid < Pc) {
        float al = ex * inv;
        g_alpha[b * Pc + tid] = al;
        float mf = (t < lengths[b] - 1) ? 1.f : 0.f;
        out_alphas[((size_t)b * Tc + t) * Pc + tid] = al * mf;
    }
}

// awe[b,d] = sum_p alpha[b,p] * features[b,p,d]
__global__ void awe_kernel(const float* __restrict__ f) {
    int idx = blockIdx.x * blockDim.x + threadIdx.x;
    if (idx >= Bc * Dc) return;
    int b = idx / Dc, d = idx % Dc;
    const float* fp = f + (size_t)b * Pc * Dc + d;
    const float* al = g_alpha + b * Pc;
    float s = 0.f;
    #pragma unroll 4
    for (int p = 0; p < Pc; p++) s += al[p] * fp[(size_t)p * Dc];
    g_awe[idx] = s;
}

// xin = [e_t (E), gate * awe (D)]
__global__ void xin_kernel(int t) {
    int idx = blockIdx.x * blockDim.x + threadIdx.x;
    if (idx >= Bc * (Ec + Dc)) return;
    int b = idx / (Ec + Dc), j = idx % (Ec + Dc);
    float v;
    if (j < Ec) v = g_eseq[((size_t)b * Tc + t) * Ec + j];
    else {
        int d = j - Ec;
        v = g_gate[b * Dc + d] * g_awe[b * Dc + d];
    }
    g_xin[idx] = v;
}

__device__ __forceinline__ float sigf(float x) { return 1.f / (1.f + expf(-x)); }

// LSTM pointwise: c_new/h_new; masked carry update; hn always written
__global__ void lstm_kernel(const int* __restrict__ lengths, int t) {
    int idx = blockIdx.x * blockDim.x + threadIdx.x;
    if (idx >= Bc * Hc) return;
    int b = idx / Hc, j = idx % Hc;
    const float* gr = g_gates + (size_t)b * 4 * Hc;
    float i_ = gr[j];
    float f_ = gr[Hc + j];
    float gg = gr[2 * Hc + j];
    float o_ = gr[3 * Hc + j];
    float cn = sigf(f_) * g_c[idx] + sigf(i_) * tanhf(gg);
    float hn = sigf(o_) * tanhf(cn);
    g_hn[idx] = hn;
    if (t < lengths[b] - 1) {
        g_h[idx] = hn;
        g_c[idx] = cn;
    }
}

// ---------------- launcher -------------------------------------------------

static void launch_gemm(const float* A, const float* W, const float* bias, float* C,
                        int M, int N, int K, int ldc, int accum, int act,
                        const int* lengths, int t) {
    dim3 grid((N + BN - 1) / BN, (M + BM - 1) / BM);
    gemm_kernel<<<grid, 256>>>(A, W, bias, C, M, N, K, ldc, accum, act, lengths, t);
}

extern "C" void kernel_launch(void* const* d_in, const int* in_sizes, int n_in,
                              void* d_out, int out_size) {
    const float* features = (const float*)d_in[0];
    const int*   captions = (const int*)d_in[1];
    const int*   lengths  = (const int*)d_in[2];
    const float* emb      = (const float*)d_in[3];
    const float* h_fc_w   = (const float*)d_in[4];
    const float* h_fc_b   = (const float*)d_in[5];
    const float* c_fc_w   = (const float*)d_in[6];
    const float* c_fc_b   = (const float*)d_in[7];
    const float* enc_w    = (const float*)d_in[8];
    const float* enc_b    = (const float*)d_in[9];
    const float* dec_w    = (const float*)d_in[10];
    const float* dec_b    = (const float*)d_in[11];
    const float* att_w    = (const float*)d_in[12];
    const float* att_b    = (const float*)d_in[13];
    const float* beta_w   = (const float*)d_in[14];
    const float* beta_b   = (const float*)d_in[15];
    const float* w_ih     = (const float*)d_in[16];
    const float* b_ih     = (const float*)d_in[17];
    const float* w_hh     = (const float*)d_in[18];
    const float* b_hh     = (const float*)d_in[19];
    const float* cls_w    = (const float*)d_in[20];
    const float* cls_b    = (const float*)d_in[21];

    float* out = (float*)d_out;
    float* y_out = out;                               // (B, T, V)
    float* a_out = out + (size_t)Bc * Tc * Vc;        // (B, T, P)

    float *meanf, *h, *c, *hn, *att1, *att2, *xin, *gates, *gate;
    cudaGetSymbolAddress((void**)&meanf, g_meanf);
    cudaGetSymbolAddress((void**)&h,     g_h);
    cudaGetSymbolAddress((void**)&c,     g_c);
    cudaGetSymbolAddress((void**)&hn,    g_hn);
    cudaGetSymbolAddress((void**)&att1,  g_att1);
    cudaGetSymbolAddress((void**)&att2,  g_att2);
    cudaGetSymbolAddress((void**)&xin,   g_xin);
    cudaGetSymbolAddress((void**)&gates, g_gates);
    cudaGetSymbolAddress((void**)&gate,  g_gate);

    // ---- precompute -------------------------------------------------------
    mean_kernel<<<(Bc * Dc + 255) / 256, 256>>>(features);
    launch_gemm(meanf, h_fc_w, h_fc_b, h, Bc, Hc, Dc, Hc, 0, 0, nullptr, 0);
    launch_gemm(meanf, c_fc_w, c_fc_b, c, Bc, Hc, Dc, Hc, 0, 0, nullptr, 0);
    // att1 = features(25088,2048) @ enc_w(2048,512) + enc_b
    launch_gemm(features, enc_w, enc_b, att1, Bc * Pc, Ac, Dc, Ac, 0, 0, nullptr, 0);
    embed_kernel<<<(Bc * Tc * Ec + 255) / 256, 256>>>(emb, captions);

    // ---- sequential decode ------------------------------------------------
    for (int t = 0; t < Tc; t++) {
        // att2 = h @ dec_w + dec_b
        launch_gemm(h, dec_w, dec_b, att2, Bc, Ac, Hc, Ac, 0, 0, nullptr, 0);
        // e = relu(att1 + att2) @ att_w + att_b
        att_score_kernel<<<dim3((Pc + 3) / 4, Bc), 128>>>(att_w, att_b);
        // alpha = softmax(e); write masked alphas output
        softmax_kernel<<<Bc, 256>>>(lengths, t, a_out);
        // awe = einsum(alpha, features)
        awe_kernel<<<(Bc * Dc + 255) / 256, 256>>>(features);
        // gate = sigmoid(h @ beta_w + beta_b)
        launch_gemm(h, beta_w, beta_b, gate, Bc, Dc, Hc, Dc, 0, 1, nullptr, 0);
        // xin = [e_t, gate*awe]
        xin_kernel<<<(Bc * (Ec + Dc) + 255) / 256, 256>>>(t);
        // gates = xin @ w_ih + b_ih + h @ w_hh + b_hh
        launch_gemm(xin, w_ih, b_ih, gates, Bc, 4 * Hc, Dc + Ec, 4 * Hc, 0, 0, nullptr, 0);
        launch_gemm(h, w_hh, b_hh, gates, Bc, 4 * Hc, Hc, 4 * Hc, 1, 0, nullptr, 0);
        // LSTM pointwise + masked state update
        lstm_kernel<<<(Bc * Hc + 255) / 256, 256>>>(lengths, t);
        // y[:, t, :] = (hn @ cls_w + cls_b) * rowmask
        launch_gemm(hn, cls_w, cls_b, y_out + (size_t)t * Vc, Bc, Vc, Hc, Tc * Vc, 0, 0, lengths, t);
    }
}

// round 7
// speedup vs baseline: 4.5964x; 4.5964x over previous
#include <cuda_runtime.h>
#include <cuda_fp16.h>
#include <math.h>
#include <stdint.h>

// Problem constants
#define Bc 128
#define Pc 196
#define Dc 2048
#define Ac 512
#define Ec 512
#define Hc 512
#define Vc 10000
#define Tc 19
#define TMAXc 20
#define KCAT 3072   // E + D + H for fused gates GEMM
#define VPAD 10048  // Vc padded to multiple of 64
#define NSPLIT 3    // split-K factor for gates GEMM

// ---------------- scratch (device globals; no allocation allowed) ----------
__device__ __half g_feat16[(size_t)Bc * Pc * Dc];     // fp16 copy of features
__device__ __half g_meanf16[Bc * Dc];
__device__ __half g_h16[Bc * Hc];
__device__ float  g_c[Bc * Hc];
__device__ __half g_hn16[Bc * Hc];
__device__ __half g_att1_16[(size_t)Bc * Pc * Ac];
__device__ __half g_eseq16[(size_t)Bc * Tc * Ec];
__device__ float  g_att2[Bc * Ac];
__device__ float  g_alpha[Bc * Pc];
__device__ float  g_awe[Bc * Dc];
__device__ __half g_gate16[Bc * Dc];
__device__ __half g_xin16[Bc * KCAT];
__device__ float  g_gates[NSPLIT][Bc * 4 * Hc];       // split-K partials
// transposed fp16 weights (K-major B operands: Bt[n][k])
__device__ __half g_hfcT[Hc * Dc];
__device__ __half g_cfcT[Hc * Dc];
__device__ __half g_encT[Ac * Dc];
__device__ __half g_decT[Ac * Hc];
__device__ __half g_betaT[Dc * Hc];
__device__ __half g_wcatT[(size_t)(4 * Hc) * KCAT];
__device__ __half g_clsT[(size_t)VPAD * Hc];          // zero-padded tail rows
__device__ float  g_bcat[4 * Hc];

// ---------------- helpers ---------------------------------------------------
__device__ __forceinline__ uint32_t smem_u32(const void* p) {
    uint32_t a;
    asm("{ .reg .u64 t; cvta.to.shared.u64 t, %1; cvt.u32.u64 %0, t; }" : "=r"(a) : "l"(p));
    return a;
}
__device__ __forceinline__ void cp16(uint32_t dst, const void* src) {
    asm volatile("cp.async.ca.shared.global [%0], [%1], 16;" :: "r"(dst), "l"(src));
}
#define CP_COMMIT() asm volatile("cp.async.commit_group;" ::: "memory")

__device__ __forceinline__ float sigf(float x) { return 1.f / (1.f + expf(-x)); }

// ---------------- mma.sync fp16 GEMM ----------------------------------------
// C[M,N] = act(A[M,K] @ Bt[N,K]^T + bias) * rowmask      (fp16 in, fp32 accum)
// M multiple of 128. N arbitrary (Bt row-padded to 64). K mult of 32*gridDim.z.
// gridDim.z > 1: slice z writes raw partial to C + z*M*ldc (no bias/act/mask).
#define ASTR 40   // smem row stride in halfs (32 data + 8 pad = 80B, conflict-free)
__global__ void __launch_bounds__(256) gemm_mma(
    const __half* __restrict__ A, const __half* __restrict__ Bt,
    const float* __restrict__ bias, float* __restrict__ C, __half* __restrict__ C16,
    int M, int N, int K, int ldc, int ld16, int act,
    const int* __restrict__ lengths, int t)
{
    __shared__ __half sA[2][128 * ASTR];
    __shared__ __half sB[2][64 * ASTR];

    const int tid = threadIdx.x;
    const int lane = tid & 31, warp = tid >> 5;
    const int wm = warp >> 2, wn = warp & 3;   // 2 x 4 warp grid
    const int row0 = blockIdx.y * 128, col0 = blockIdx.x * 64;

    const int kchunk = K / gridDim.z;
    const __half* Ab = A + (size_t)row0 * K + (size_t)blockIdx.z * kchunk;
    const __half* Bb = Bt + (size_t)col0 * K + (size_t)blockIdx.z * kchunk;
    const int nk = kchunk >> 5;

    const uint32_t sAu = smem_u32(sA);
    const uint32_t sBu = smem_u32(sB);

    float acc[4][2][4];
    #pragma unroll
    for (int i = 0; i < 4; i++)
        #pragma unroll
        for (int j = 0; j < 2; j++)
            #pragma unroll
            for (int e = 0; e < 4; e++) acc[i][j][e] = 0.f;

    // ldmatrix address components
    const int aRow = wm * 64 + (lane & 15);
    const int aCol = (lane >= 16) ? 8 : 0;
    const int bRow = wn * 16 + (lane & 7);
    const int bCol = ((lane & 15) >= 8) ? 8 : 0;

    // ---- prologue load stage 0 ----
    {
        int c = tid;
        #pragma unroll
        for (int j = 0; j < 2; j++, c += 256) {
            int r = c >> 2, q = c & 3;
            cp16(sAu + (uint32_t)(r * ASTR + q * 8) * 2, Ab + (size_t)r * K + q * 8);
        }
        int r = tid >> 2, q = tid & 3;
        cp16(sBu + (uint32_t)(r * ASTR + q * 8) * 2, Bb + (size_t)r * K + q * 8);
    }
    CP_COMMIT();

    for (int i = 0; i < nk; i++) {
        int buf = i & 1;
        if (i + 1 < nk) {
            int nbuf = buf ^ 1;
            int k0 = (i + 1) << 5;
            int c = tid;
            #pragma unroll
            for (int j = 0; j < 2; j++, c += 256) {
                int r = c >> 2, q = c & 3;
                cp16(sAu + (uint32_t)(nbuf * 128 * ASTR + r * ASTR + q * 8) * 2,
                     Ab + (size_t)r * K + k0 + q * 8);
            }
            int r = tid >> 2, q = tid & 3;
            cp16(sBu + (uint32_t)(nbuf * 64 * ASTR + r * ASTR + q * 8) * 2,
                 Bb + (size_t)r * K + k0 + q * 8);
            CP_COMMIT();
            asm volatile("cp.async.wait_group 1;" ::: "memory");
        } else {
            asm volatile("cp.async.wait_group 0;" ::: "memory");
        }
        __syncthreads();

        uint32_t baseA = sAu + (uint32_t)(buf * 128 * ASTR) * 2;
        uint32_t baseB = sBu + (uint32_t)(buf * 64 * ASTR) * 2;
        #pragma unroll
        for (int ks = 0; ks < 32; ks += 16) {
            uint32_t a[4][4], b[2][2];
            #pragma unroll
            for (int mf = 0; mf < 4; mf++) {
                uint32_t addr = baseA + (uint32_t)((aRow + mf * 16) * ASTR + ks + aCol) * 2;
                asm volatile("ldmatrix.sync.aligned.m8n8.x4.shared.b16 {%0,%1,%2,%3}, [%4];"
                             : "=r"(a[mf][0]), "=r"(a[mf][1]), "=r"(a[mf][2]), "=r"(a[mf][3])
                             : "r"(addr));
            }
            #pragma unroll
            for (int nf = 0; nf < 2; nf++) {
                uint32_t addr = baseB + (uint32_t)((bRow + nf * 8) * ASTR + ks + bCol) * 2;
                asm volatile("ldmatrix.sync.aligned.m8n8.x2.shared.b16 {%0,%1}, [%2];"
                             : "=r"(b[nf][0]), "=r"(b[nf][1]) : "r"(addr));
            }
            #pragma unroll
            for (int mf = 0; mf < 4; mf++)
                #pragma unroll
                for (int nf = 0; nf < 2; nf++) {
                    float* cc = acc[mf][nf];
                    asm volatile(
                        "mma.sync.aligned.m16n8k16.row.col.f32.f16.f16.f32 "
                        "{%0,%1,%2,%3}, {%4,%5,%6,%7}, {%8,%9}, {%0,%1,%2,%3};"
                        : "+f"(cc[0]), "+f"(cc[1]), "+f"(cc[2]), "+f"(cc[3])
                        : "r"(a[mf][0]), "r"(a[mf][1]), "r"(a[mf][2]), "r"(a[mf][3]),
                          "r"(b[nf][0]), "r"(b[nf][1]));
                }
        }
        __syncthreads();
    }

    // ---- epilogue ----
    const bool partial = (gridDim.z > 1);
    float* Cz = partial ? (C + (size_t)blockIdx.z * M * ldc) : C;
    const int mbase = row0 + wm * 64;
    const int nbase = col0 + wn * 16;
    #pragma unroll
    for (int mf = 0; mf < 4; mf++) {
        #pragma unroll
        for (int hr = 0; hr < 2; hr++) {
            int m = mbase + mf * 16 + (lane >> 2) + hr * 8;
            float mk = 1.f;
            if (lengths) mk = (t < lengths[m] - 1) ? 1.f : 0.f;
            #pragma unroll
            for (int nf = 0; nf < 2; nf++) {
                #pragma unroll
                for (int e = 0; e < 2; e++) {
                    int n = nbase + nf * 8 + (lane & 3) * 2 + e;
                    if (n < N) {
                        float v = acc[mf][nf][hr * 2 + e];
                        if (partial) {
                            Cz[(size_t)m * ldc + n] = v;
                        } else {
                            if (bias) v += bias[n];
                            if (act) v = sigf(v);
                            v *= mk;
                            if (C)   C[(size_t)m * ldc + n] = v;
                            if (C16) C16[(size_t)m * ld16 + n] = __float2half_rn(v);
                        }
                    }
                }
            }
        }
    }
}

// ---------------- support kernels -------------------------------------------

__global__ void f32to16_kernel(const float* __restrict__ in, __half* __restrict__ out, int n2) {
    int i = blockIdx.x * blockDim.x + threadIdx.x;
    if (i < n2) {
        float2 v = ((const float2*)in)[i];
        ((__half2*)out)[i] = __floats2half2_rn(v.x, v.y);
    }
}

// in fp32 [K,N] row-major -> out fp16 [n][out_ld] at k_off
__global__ void transpose16_kernel(const float* __restrict__ in, __half* __restrict__ out,
                                   int K, int N, int out_ld, int k_off) {
    __shared__ float tile[32][33];
    int kb = blockIdx.y * 32, nb = blockIdx.x * 32;
    int x = threadIdx.x, y = threadIdx.y;   // (32, 8)
    #pragma unroll
    for (int j = 0; j < 32; j += 8) {
        int k = kb + y + j, n = nb + x;
        tile[y + j][x] = (k < K && n < N) ? in[(size_t)k * N + n] : 0.f;
    }
    __syncthreads();
    #pragma unroll
    for (int j = 0; j < 32; j += 8) {
        int n = nb + y + j, k = kb + x;
        if (n < N && k < K) out[(size_t)n * out_ld + k_off + k] = __float2half_rn(tile[x][y + j]);
    }
}

// zero-pad the clsT tail rows (Vc..VPAD)
__global__ void clspad_kernel() {
    int i = blockIdx.x * blockDim.x + threadIdx.x;
    int total = (VPAD - Vc) * Hc;
    if (i < total) g_clsT[(size_t)Vc * Hc + i] = __float2half_rn(0.f);
}

__global__ void bias_cat_kernel(const float* __restrict__ a, const float* __restrict__ b) {
    int i = blockIdx.x * blockDim.x + threadIdx.x;
    if (i < 4 * Hc) g_bcat[i] = a[i] + b[i];
}

__global__ void mean_kernel(const float* __restrict__ f) {
    int idx = blockIdx.x * blockDim.x + threadIdx.x;
    if (idx >= Bc * Dc) return;
    int b = idx / Dc, d = idx % Dc;
    const float* p = f + (size_t)b * Pc * Dc + d;
    float s = 0.f;
    #pragma unroll 4
    for (int i = 0; i < Pc; i++) s += p[(size_t)i * Dc];
    g_meanf16[idx] = __float2half_rn(s * (1.0f / Pc));
}

__global__ void embed_kernel(const float* __restrict__ emb, const int* __restrict__ cap) {
    int idx = blockIdx.x * blockDim.x + threadIdx.x;
    if (idx >= Bc * Tc * Ec) return;
    int j = idx % Ec;
    int bt = idx / Ec;
    int t = bt % Tc;
    int b = bt / Tc;
    int tok = cap[b * TMAXc + t];
    g_eseq16[idx] = __float2half_rn(emb[(size_t)tok * Ec + j]);
}

// e[b,p] = sum_a relu(att1[b,p,a] + att2[b,a]) * att_w[a] + att_b
__global__ void att_score_kernel(const float* __restrict__ att_w, const float* __restrict__ att_b) {
    __shared__ float s2[Ac];
    __shared__ float sw[Ac];
    int b = blockIdx.y;
    int tid = threadIdx.x;
    for (int i = tid; i < Ac; i += 128) {
        s2[i] = g_att2[b * Ac + i];
        sw[i] = att_w[i];
    }
    __syncthreads();
    int warp = tid >> 5, lane = tid & 31;
    int p = blockIdx.x * 4 + warp;
    if (p < Pc) {
        const __half* a1 = g_att1_16 + ((size_t)b * Pc + p) * Ac;
        float s = 0.f;
        #pragma unroll 4
        for (int a = lane; a < Ac; a += 32) {
            float v = __half2float(a1[a]) + s2[a];
            v = fmaxf(v, 0.f);
            s += v * sw[a];
        }
        #pragma unroll
        for (int o = 16; o > 0; o >>= 1) s += __shfl_xor_sync(0xffffffffu, s, o);
        if (lane == 0) g_alpha[b * Pc + p] = s + att_b[0];
    }
}

__global__ void softmax_kernel(const int* __restrict__ lengths, int t, float* __restrict__ out_alphas) {
    int b = blockIdx.x;
    int tid = threadIdx.x;  // 256
    __shared__ float red[256];
    float v = (tid < Pc) ? g_alpha[b * Pc + tid] : -1e30f;
    red[tid] = v;
    __syncthreads();
    for (int s = 128; s > 0; s >>= 1) {
        if (tid < s) red[tid] = fmaxf(red[tid], red[tid + s]);
        __syncthreads();
    }
    float mx = red[0];
    __syncthreads();
    float ex = (tid < Pc) ? expf(v - mx) : 0.f;
    red[tid] = ex;
    __syncthreads();
    for (int s = 128; s > 0; s >>= 1) {
        if (tid < s) red[tid] += red[tid + s];
        __syncthreads();
    }
    float inv = 1.0f / red[0];
    if (tid < Pc) {
        float al = ex * inv;
        g_alpha[b * Pc + tid] = al;
        float mf = (t < lengths[b] - 1) ? 1.f : 0.f;
        out_alphas[((size_t)b * Tc + t) * Pc + tid] = al * mf;
    }
}

// awe[b,d] = sum_p alpha[b,p] * feat16[b,p,d]  (half2 vectorized)
__global__ void awe_kernel() {
    int idx = blockIdx.x * blockDim.x + threadIdx.x;
    if (idx >= Bc * Dc / 2) return;
    int b = idx / (Dc / 2), d2 = idx % (Dc / 2);
    const __half2* fp = ((const __half2*)g_feat16) + ((size_t)b * Pc * Dc) / 2 + d2;
    const float* al = g_alpha + b * Pc;
    float sx = 0.f, sy = 0.f;
    #pragma unroll 4
    for (int p = 0; p < Pc; p++) {
        float a = al[p];
        float2 v = __half22float2(fp[(size_t)p * (Dc / 2)]);
        sx += a * v.x;
        sy += a * v.y;
    }
    ((float2*)g_awe)[idx] = make_float2(sx, sy);
}

// xin = [e_t (E), gate*awe (D), h (H)]  -> fp16
__global__ void xin_kernel(int t) {
    int idx = blockIdx.x * blockDim.x + threadIdx.x;
    if (idx >= Bc * KCAT) return;
    int b = idx / KCAT, j = idx % KCAT;
    __half v;
    if (j < Ec) v = g_eseq16[((size_t)b * Tc + t) * Ec + j];
    else if (j < Ec + Dc) {
        int d = j - Ec;
        v = __float2half_rn(__half2float(g_gate16[b * Dc + d]) * g_awe[b * Dc + d]);
    } else {
        v = g_h16[b * Hc + (j - Ec - Dc)];
    }
    g_xin16[idx] = v;
}

// LSTM pointwise: sums NSPLIT gate partials + bcat bias; masked carry update
__global__ void lstm_kernel(const int* __restrict__ lengths, int t) {
    int idx = blockIdx.x * blockDim.x + threadIdx.x;
    if (idx >= Bc * Hc) return;
    int b = idx / Hc, j = idx % Hc;
    size_t base = (size_t)b * 4 * Hc;
    float i_ = g_bcat[j],          f_ = g_bcat[Hc + j];
    float gg = g_bcat[2 * Hc + j], o_ = g_bcat[3 * Hc + j];
    #pragma unroll
    for (int z = 0; z < NSPLIT; z++) {
        const float* gr = g_gates[z] + base;
        i_ += gr[j];
        f_ += gr[Hc + j];
        gg += gr[2 * Hc + j];
        o_ += gr[3 * Hc + j];
    }
    float cn = sigf(f_) * g_c[idx] + sigf(i_) * tanhf(gg);
    float hn = sigf(o_) * tanhf(cn);
    g_hn16[idx] = __float2half_rn(hn);
    if (t < lengths[b] - 1) {
        g_h16[idx] = __float2half_rn(hn);
        g_c[idx] = cn;
    }
}

// ---------------- launcher ---------------------------------------------------

static void gemmL(const __half* A, const __half* Bt, const float* bias,
                  float* C, __half* C16, int M, int N, int K, int ldc, int ld16,
                  int act, const int* lengths, int t, int splitk) {
    dim3 grid((N + 63) / 64, M / 128, splitk);
    gemm_mma<<<grid, 256>>>(A, Bt, bias, C, C16, M, N, K, ldc, ld16, act, lengths, t);
}
static void transL(const float* in, __half* out, int K, int N, int out_ld, int k_off) {
    dim3 grid((N + 31) / 32, (K + 31) / 32);
    transpose16_kernel<<<grid, dim3(32, 8)>>>(in, out, K, N, out_ld, k_off);
}

extern "C" void kernel_launch(void* const* d_in, const int* in_sizes, int n_in,
                              void* d_out, int out_size) {
    const float* features = (const float*)d_in[0];
    const int*   captions = (const int*)d_in[1];
    const int*   lengths  = (const int*)d_in[2];
    const float* emb      = (const float*)d_in[3];
    const float* h_fc_w   = (const float*)d_in[4];
    const float* h_fc_b   = (const float*)d_in[5];
    const float* c_fc_w   = (const float*)d_in[6];
    const float* c_fc_b   = (const float*)d_in[7];
    const float* enc_w    = (const float*)d_in[8];
    const float* enc_b    = (const float*)d_in[9];
    const float* dec_w    = (const float*)d_in[10];
    const float* dec_b    = (const float*)d_in[11];
    const float* att_w    = (const float*)d_in[12];
    const float* att_b    = (const float*)d_in[13];
    const float* beta_w   = (const float*)d_in[14];
    const float* beta_b   = (const float*)d_in[15];
    const float* w_ih     = (const float*)d_in[16];
    const float* b_ih     = (const float*)d_in[17];
    const float* w_hh     = (const float*)d_in[18];
    const float* b_hh     = (const float*)d_in[19];
    const float* cls_w    = (const float*)d_in[20];
    const float* cls_b    = (const float*)d_in[21];

    float* out = (float*)d_out;
    float* y_out = out;                               // (B, T, V)
    float* a_out = out + (size_t)Bc * Tc * Vc;        // (B, T, P)

    __half *feat16, *meanf16, *h16, *hn16, *att1_16, *gate16, *xin16;
    __half *hfcT, *cfcT, *encT, *decT, *betaT, *wcatT, *clsT;
    float *cst, *att2, *gates;
    cudaGetSymbolAddress((void**)&feat16,  g_feat16);
    cudaGetSymbolAddress((void**)&meanf16, g_meanf16);
    cudaGetSymbolAddress((void**)&h16,     g_h16);
    cudaGetSymbolAddress((void**)&hn16,    g_hn16);
    cudaGetSymbolAddress((void**)&att1_16, g_att1_16);
    cudaGetSymbolAddress((void**)&gate16,  g_gate16);
    cudaGetSymbolAddress((void**)&xin16,   g_xin16);
    cudaGetSymbolAddress((void**)&hfcT,    g_hfcT);
    cudaGetSymbolAddress((void**)&cfcT,    g_cfcT);
    cudaGetSymbolAddress((void**)&encT,    g_encT);
    cudaGetSymbolAddress((void**)&decT,    g_decT);
    cudaGetSymbolAddress((void**)&betaT,   g_betaT);
    cudaGetSymbolAddress((void**)&wcatT,   g_wcatT);
    cudaGetSymbolAddress((void**)&clsT,    g_clsT);
    cudaGetSymbolAddress((void**)&cst,     g_c);
    cudaGetSymbolAddress((void**)&att2,    g_att2);
    cudaGetSymbolAddress((void**)&gates,   g_gates);

    // ---- prologue --------------------------------------------------------
    f32to16_kernel<<<((Bc * Pc * Dc / 2) + 255) / 256, 256>>>(features, feat16, Bc * Pc * Dc / 2);
    transL(h_fc_w, hfcT, Dc, Hc, Dc, 0);
    transL(c_fc_w, cfcT, Dc, Hc, Dc, 0);
    transL(enc_w,  encT, Dc, Ac, Dc, 0);
    transL(dec_w,  decT, Hc, Ac, Hc, 0);
    transL(beta_w, betaT, Hc, Dc, Hc, 0);
    transL(w_ih,   wcatT, Dc + Ec, 4 * Hc, KCAT, 0);
    transL(w_hh,   wcatT, Hc, 4 * Hc, KCAT, Dc + Ec);
    transL(cls_w,  clsT, Hc, Vc, Hc, 0);
    clspad_kernel<<<(((VPAD - Vc) * Hc) + 255) / 256, 256>>>();
    bias_cat_kernel<<<(4 * Hc + 255) / 256, 256>>>(b_ih, b_hh);
    mean_kernel<<<(Bc * Dc + 255) / 256, 256>>>(features);
    embed_kernel<<<(Bc * Tc * Ec + 255) / 256, 256>>>(emb, captions);

    // h0/c0 ; att1 (fp16-only output)
    gemmL(meanf16, hfcT, h_fc_b, nullptr, h16, Bc, Hc, Dc, 0, Hc, 0, nullptr, 0, 1);
    gemmL(meanf16, cfcT, c_fc_b, cst, nullptr, Bc, Hc, Dc, Hc, 0, 0, nullptr, 0, 1);
    gemmL(feat16, encT, enc_b, nullptr, att1_16, Bc * Pc, Ac, Dc, 0, Ac, 0, nullptr, 0, 1);

    // ---- sequential decode -----------------------------------------------
    for (int t = 0; t < Tc; t++) {
        gemmL(h16, decT, dec_b, att2, nullptr, Bc, Ac, Hc, Ac, 0, 0, nullptr, 0, 1);
        att_score_kernel<<<dim3((Pc + 3) / 4, Bc), 128>>>(att_w, att_b);
        softmax_kernel<<<Bc, 256>>>(lengths, t, a_out);
        awe_kernel<<<((Bc * Dc / 2) + 255) / 256, 256>>>();
        gemmL(h16, betaT, beta_b, nullptr, gate16, Bc, Dc, Hc, 0, Dc, 1, nullptr, 0, 1);
        xin_kernel<<<(Bc * KCAT + 255) / 256, 256>>>(t);
        gemmL(xin16, wcatT, nullptr, gates, nullptr, Bc, 4 * Hc, KCAT, 4 * Hc, 0, 0, nullptr, 0, NSPLIT);
        lstm_kernel<<<(Bc * Hc + 255) / 256, 256>>>(lengths, t);
        gemmL(hn16, clsT, cls_b, y_out + (size_t)t * Vc, nullptr, Bc, Vc, Hc, Tc * Vc, 0, 0, lengths, t, 1);
    }
}

// round 9
// speedup vs baseline: 4.7812x; 1.0402x over previous
#include <cuda_runtime.h>
#include <cuda_fp16.h>
#include <math.h>
#include <stdint.h>

// Problem constants
#define Bc 128
#define Pc 196
#define Dc 2048
#define Ac 512
#define Ec 512
#define Hc 512
#define Vc 10000
#define Tc 19
#define TMAXc 20
#define KCAT 3072   // E + D + H for fused gates GEMM
#define NDB 2560    // A + D for merged dec+beta GEMM

// ---------------- scratch (device globals; no allocation allowed) ----------
__device__ __half g_feat16[(size_t)Bc * Pc * Dc];     // fp16 copy of features
__device__ __half g_meanf16[Bc * Dc];
__device__ __half g_h16[Bc * Hc];
__device__ float  g_c[Bc * Hc];
__device__ __half g_hn16[Bc * Hc];
__device__ __half g_att1_16[(size_t)Bc * Pc * Ac];
__device__ __half g_eseq16[(size_t)Bc * Tc * Ec];
__device__ float  g_att2[Bc * Ac];
__device__ float  g_alpha[Bc * Pc];
__device__ __half g_gate16[Bc * Dc];
__device__ __half g_xin16[Bc * KCAT];
__device__ float  g_gates[Bc * 4 * Hc];
// transposed fp16 weights (K-major B operands: Bt[n][k])
__device__ __half g_hfcT[Hc * Dc];
__device__ __half g_cfcT[Hc * Dc];
__device__ __half g_encT[Ac * Dc];
__device__ __half g_dbT[(size_t)NDB * Hc];            // [decT(512) ; betaT(2048)]
__device__ float  g_dbbias[NDB];
__device__ __half g_wcatT[(size_t)(4 * Hc) * KCAT];
__device__ __half g_clsT[(size_t)Vc * Hc];
__device__ float  g_bcat[4 * Hc];

// ---------------- helpers ---------------------------------------------------
__device__ __forceinline__ uint32_t smem_u32(const void* p) {
    uint32_t a;
    asm("{ .reg .u64 t; cvta.to.shared.u64 t, %1; cvt.u32.u64 %0, t; }" : "=r"(a) : "l"(p));
    return a;
}
__device__ __forceinline__ void cp16(uint32_t dst, const void* src) {
    asm volatile("cp.async.ca.shared.global [%0], [%1], 16;" :: "r"(dst), "l"(src));
}
#define CP_COMMIT() asm volatile("cp.async.commit_group;" ::: "memory")

__device__ __forceinline__ float sigf(float x) { return 1.f / (1.f + expf(-x)); }

// ---------------- mma.sync fp16 GEMM ----------------------------------------
// C[M,N] = epi(A[M,K] @ Bt[N,K]^T + bias)      (fp16 in, fp32 accum)
// M multiple of BM. K multiple of 32. N arbitrary (Bt rows padded to tile).
// mode: 0 = plain (bias, C/C16, rowmask), 1 = sigmoid, 2 = decbeta route.
#define ASTR 40   // smem row stride in halfs (32 data + 8 pad = 80B, conflict-free)
template<int BM>
__global__ void __launch_bounds__(256) gemm_mma(
    const __half* __restrict__ A, const __half* __restrict__ Bt,
    const float* __restrict__ bias, float* __restrict__ C, __half* __restrict__ C16,
    int M, int N, int K, int ldc, int ld16, int mode,
    const int* __restrict__ lengths, int t)
{
    __shared__ __half sA[2][BM * ASTR];
    __shared__ __half sB[2][64 * ASTR];

    const int tid = threadIdx.x;
    const int lane = tid & 31, warp = tid >> 5;
    const int wm = warp >> 2, wn = warp & 3;   // 2 x 4 warp grid
    const int row0 = blockIdx.y * BM, col0 = blockIdx.x * 64;
    constexpr int MFRAG = BM / 32;             // 16-row frags per warp

    const __half* Ab = A + (size_t)row0 * K;
    const __half* Bb = Bt + (size_t)col0 * K;
    const int nk = K >> 5;

    const uint32_t sAu = smem_u32(sA);
    const uint32_t sBu = smem_u32(sB);

    float acc[MFRAG][2][4];
    #pragma unroll
    for (int i = 0; i < MFRAG; i++)
        #pragma unroll
        for (int j = 0; j < 2; j++)
            #pragma unroll
            for (int e = 0; e < 4; e++) acc[i][j][e] = 0.f;

    // ldmatrix address components
    const int aRow = wm * (BM / 2) + (lane & 15);
    const int aCol = (lane >= 16) ? 8 : 0;
    const int bRow = wn * 16 + (lane & 7);
    const int bCol = ((lane & 15) >= 8) ? 8 : 0;

    // ---- prologue load stage 0 ----
    {
        #pragma unroll
        for (int l = 0; l < BM / 64; l++) {
            int c = tid + l * 256;
            int r = c >> 2, q = c & 3;
            cp16(sAu + (uint32_t)(r * ASTR + q * 8) * 2, Ab + (size_t)r * K + q * 8);
        }
        int r = tid >> 2, q = tid & 3;
        cp16(sBu + (uint32_t)(r * ASTR + q * 8) * 2, Bb + (size_t)r * K + q * 8);
    }
    CP_COMMIT();

    for (int i = 0; i < nk; i++) {
        int buf = i & 1;
        if (i + 1 < nk) {
            int nbuf = buf ^ 1;
            int k0 = (i + 1) << 5;
            #pragma unroll
            for (int l = 0; l < BM / 64; l++) {
                int c = tid + l * 256;
                int r = c >> 2, q = c & 3;
                cp16(sAu + (uint32_t)(nbuf * BM * ASTR + r * ASTR + q * 8) * 2,
                     Ab + (size_t)r * K + k0 + q * 8);
            }
            int r = tid >> 2, q = tid & 3;
            cp16(sBu + (uint32_t)(nbuf * 64 * ASTR + r * ASTR + q * 8) * 2,
                 Bb + (size_t)r * K + k0 + q * 8);
            CP_COMMIT();
            asm volatile("cp.async.wait_group 1;" ::: "memory");
        } else {
            asm volatile("cp.async.wait_group 0;" ::: "memory");
        }
        __syncthreads();

        uint32_t baseA = sAu + (uint32_t)(buf * BM * ASTR) * 2;
        uint32_t baseB = sBu + (uint32_t)(buf * 64 * ASTR) * 2;
        #pragma unroll
        for (int ks = 0; ks < 32; ks += 16) {
            uint32_t a[MFRAG][4], b[2][2];
            #pragma unroll
            for (int mf = 0; mf < MFRAG; mf++) {
                uint32_t addr = baseA + (uint32_t)((aRow + mf * 16) * ASTR + ks + aCol) * 2;
                asm volatile("ldmatrix.sync.aligned.m8n8.x4.shared.b16 {%0,%1,%2,%3}, [%4];"
                             : "=r"(a[mf][0]), "=r"(a[mf][1]), "=r"(a[mf][2]), "=r"(a[mf][3])
                             : "r"(addr));
            }
            #pragma unroll
            for (int nf = 0; nf < 2; nf++) {
                uint32_t addr = baseB + (uint32_t)((bRow + nf * 8) * ASTR + ks + bCol) * 2;
                asm volatile("ldmatrix.sync.aligned.m8n8.x2.shared.b16 {%0,%1}, [%2];"
                             : "=r"(b[nf][0]), "=r"(b[nf][1]) : "r"(addr));
            }
            #pragma unroll
            for (int mf = 0; mf < MFRAG; mf++)
                #pragma unroll
                for (int nf = 0; nf < 2; nf++) {
                    float* cc = acc[mf][nf];
                    asm volatile(
                        "mma.sync.aligned.m16n8k16.row.col.f32.f16.f16.f32 "
                        "{%0,%1,%2,%3}, {%4,%5,%6,%7}, {%8,%9}, {%0,%1,%2,%3};"
                        : "+f"(cc[0]), "+f"(cc[1]), "+f"(cc[2]), "+f"(cc[3])
                        : "r"(a[mf][0]), "r"(a[mf][1]), "r"(a[mf][2]), "r"(a[mf][3]),
                          "r"(b[nf][0]), "r"(b[nf][1]));
                }
        }
        __syncthreads();
    }

    // ---- epilogue ----
    const int mbase = row0 + wm * (BM / 2);
    const int nbase = col0 + wn * 16;
    #pragma unroll
    for (int mf = 0; mf < MFRAG; mf++) {
        #pragma unroll
        for (int hr = 0; hr < 2; hr++) {
            int m = mbase + mf * 16 + (lane >> 2) + hr * 8;
            float mk = 1.f;
            if (lengths) mk = (t < lengths[m] - 1) ? 1.f : 0.f;
            #pragma unroll
            for (int nf = 0; nf < 2; nf++) {
                #pragma unroll
                for (int e = 0; e < 2; e++) {
                    int n = nbase + nf * 8 + (lane & 3) * 2 + e;
                    if (n < N) {
                        float v = acc[mf][nf][hr * 2 + e];
                        if (bias) v += bias[n];
                        if (mode == 2) {
                            if (n < Ac) g_att2[m * Ac + n] = v;
                            else g_gate16[m * Dc + (n - Ac)] = __float2half_rn(sigf(v));
                        } else {
                            if (mode == 1) v = sigf(v);
                            v *= mk;
                            if (C)   C[(size_t)m * ldc + n] = v;
                            if (C16) C16[(size_t)m * ld16 + n] = __float2half_rn(v);
                        }
                    }
                }
            }
        }
    }
}

// ---------------- support kernels -------------------------------------------

__global__ void f32to16_kernel(const float* __restrict__ in, __half* __restrict__ out, int n2) {
    int i = blockIdx.x * blockDim.x + threadIdx.x;
    if (i < n2) {
        float2 v = ((const float2*)in)[i];
        ((__half2*)out)[i] = __floats2half2_rn(v.x, v.y);
    }
}

// in fp32 [K,N] row-major -> out fp16 [n][out_ld] at k_off
__global__ void transpose16_kernel(const float* __restrict__ in, __half* __restrict__ out,
                                   int K, int N, int out_ld, int k_off) {
    __shared__ float tile[32][33];
    int kb = blockIdx.y * 32, nb = blockIdx.x * 32;
    int x = threadIdx.x, y = threadIdx.y;   // (32, 8)
    #pragma unroll
    for (int j = 0; j < 32; j += 8) {
        int k = kb + y + j, n = nb + x;
        tile[y + j][x] = (k < K && n < N) ? in[(size_t)k * N + n] : 0.f;
    }
    __syncthreads();
    #pragma unroll
    for (int j = 0; j < 32; j += 8) {
        int n = nb + y + j, k = kb + x;
        if (n < N && k < K) out[(size_t)n * out_ld + k_off + k] = __float2half_rn(tile[x][y + j]);
    }
}

__global__ void bias_prep_kernel(const float* __restrict__ bi, const float* __restrict__ bh,
                                 const float* __restrict__ db, const float* __restrict__ bb) {
    int i = blockIdx.x * blockDim.x + threadIdx.x;
    if (i < 4 * Hc) g_bcat[i] = bi[i] + bh[i];
    if (i < NDB) g_dbbias[i] = (i < Ac) ? db[i] : bb[i - Ac];
}

__global__ void mean_kernel(const float* __restrict__ f) {
    int idx = blockIdx.x * blockDim.x + threadIdx.x;
    if (idx >= Bc * Dc) return;
    int b = idx / Dc, d = idx % Dc;
    const float* p = f + (size_t)b * Pc * Dc + d;
    float s = 0.f;
    #pragma unroll 4
    for (int i = 0; i < Pc; i++) s += p[(size_t)i * Dc];
    g_meanf16[idx] = __float2half_rn(s * (1.0f / Pc));
}

__global__ void embed_kernel(const float* __restrict__ emb, const int* __restrict__ cap) {
    int idx = blockIdx.x * blockDim.x + threadIdx.x;
    if (idx >= Bc * Tc * Ec) return;
    int j = idx % Ec;
    int bt = idx / Ec;
    int t = bt % Tc;
    int b = bt / Tc;
    int tok = cap[b * TMAXc + t];
    g_eseq16[idx] = __float2half_rn(emb[(size_t)tok * Ec + j]);
}

// fused: e = relu(att1 + att2) @ att_w + att_b ; alpha = softmax(e) ; masked out
__global__ void __launch_bounds__(512) att_softmax_kernel(
    const float* __restrict__ att_w, const float* __restrict__ att_b,
    const int* __restrict__ lengths, int t, float* __restrict__ out_alphas)
{
    __shared__ float s2[Ac];
    __shared__ float sw[Ac];
    __shared__ float se[224];
    __shared__ float red[256];
    int b = blockIdx.x;
    int tid = threadIdx.x;   // 512
    s2[tid] = g_att2[b * Ac + tid];
    sw[tid] = att_w[tid];
    __syncthreads();

    int warp = tid >> 5, lane = tid & 31;
    float attb = att_b[0];
    for (int p = warp; p < Pc; p += 16) {
        const __half2* a1 = (const __half2*)(g_att1_16 + ((size_t)b * Pc + p) * Ac);
        float s = 0.f;
        #pragma unroll
        for (int k = 0; k < 8; k++) {
            int h2i = lane + 32 * k;
            float2 v = __half22float2(a1[h2i]);
            int a0 = 2 * h2i;
            s += fmaxf(v.x + s2[a0], 0.f) * sw[a0];
            s += fmaxf(v.y + s2[a0 + 1], 0.f) * sw[a0 + 1];
        }
        #pragma unroll
        for (int o = 16; o > 0; o >>= 1) s += __shfl_xor_sync(0xffffffffu, s, o);
        if (lane == 0) se[p] = s + attb;
    }
    __syncthreads();

    float v = (tid < Pc) ? se[tid] : -1e30f;
    if (tid < 256) red[tid] = v;
    __syncthreads();
    for (int s = 128; s > 0; s >>= 1) {
        if (tid < s) red[tid] = fmaxf(red[tid], red[tid + s]);
        __syncthreads();
    }
    float mx = red[0];
    __syncthreads();
    float ex = (tid < Pc) ? expf(v - mx) : 0.f;
    if (tid < 256) red[tid] = ex;
    __syncthreads();
    for (int s = 128; s > 0; s >>= 1) {
        if (tid < s) red[tid] += red[tid + s];
        __syncthreads();
    }
    float inv = 1.0f / red[0];
    if (tid < Pc) {
        float al = ex * inv;
        g_alpha[b * Pc + tid] = al;
        float mf = (t < lengths[b] - 1) ? 1.f : 0.f;
        out_alphas[((size_t)b * Tc + t) * Pc + tid] = al * mf;
    }
}

// fused: xin = [e_t | gate * (alpha @ features) | h]  (all fp16, half2 lanes)
#define AWE_N   (Bc * Dc / 2)
#define ECPY_N  (Bc * Ec / 2)
#define HCPY_N  (Bc * Hc / 2)
__global__ void awe_xin_kernel(int t) {
    int idx = blockIdx.x * blockDim.x + threadIdx.x;
    __half2* xin2 = (__half2*)g_xin16;
    if (idx < AWE_N) {
        int b = idx / (Dc / 2), d2 = idx % (Dc / 2);
        const __half2* fp = ((const __half2*)g_feat16) + ((size_t)b * Pc * Dc) / 2 + d2;
        const float* al = g_alpha + b * Pc;
        float sx = 0.f, sy = 0.f;
        #pragma unroll 4
        for (int p = 0; p < Pc; p++) {
            float a = al[p];
            float2 v = __half22float2(fp[(size_t)p * (Dc / 2)]);
            sx += a * v.x;
            sy += a * v.y;
        }
        float2 g = __half22float2(((const __half2*)g_gate16)[b * (Dc / 2) + d2]);
        xin2[b * (KCAT / 2) + (Ec / 2) + d2] = __floats2half2_rn(sx * g.x, sy * g.y);
    } else if (idx < AWE_N + ECPY_N) {
        int i = idx - AWE_N;
        int b = i / (Ec / 2), j2 = i % (Ec / 2);
        xin2[b * (KCAT / 2) + j2] =
            ((const __half2*)g_eseq16)[((size_t)b * Tc + t) * (Ec / 2) + j2];
    } else if (idx < AWE_N + ECPY_N + HCPY_N) {
        int i = idx - AWE_N - ECPY_N;
        int b = i / (Hc / 2), j2 = i % (Hc / 2);
        xin2[b * (KCAT / 2) + ((Ec + Dc) / 2) + j2] =
            ((const __half2*)g_h16)[b * (Hc / 2) + j2];
    }
}

// LSTM pointwise (gates already include bias); masked carry update
__global__ void lstm_kernel(const int* __restrict__ lengths, int t) {
    int idx = blockIdx.x * blockDim.x + threadIdx.x;
    if (idx >= Bc * Hc) return;
    int b = idx / Hc, j = idx % Hc;
    const float* gr = g_gates + (size_t)b * 4 * Hc;
    float i_ = gr[j];
    float f_ = gr[Hc + j];
    float gg = gr[2 * Hc + j];
    float o_ = gr[3 * Hc + j];
    float cn = sigf(f_) * g_c[idx] + sigf(i_) * tanhf(gg);
    float hn = sigf(o_) * tanhf(cn);
    g_hn16[idx] = __float2half_rn(hn);
    if (t < lengths[b] - 1) {
        g_h16[idx] = __float2half_rn(hn);
        g_c[idx] = cn;
    }
}

// ---------------- launcher ---------------------------------------------------

static void gemm128(const __half* A, const __half* Bt, const float* bias,
                    float* C, __half* C16, int M, int N, int K, int ldc, int ld16,
                    int mode, const int* lengths, int t) {
    dim3 grid((N + 63) / 64, M / 128);
    gemm_mma<128><<<grid, 256>>>(A, Bt, bias, C, C16, M, N, K, ldc, ld16, mode, lengths, t);
}
static void gemm64(const __half* A, const __half* Bt, const float* bias,
                   float* C, __half* C16, int M, int N, int K, int ldc, int ld16,
                   int mode, const int* lengths, int t) {
    dim3 grid((N + 63) / 64, M / 64);
    gemm_mma<64><<<grid, 256>>>(A, Bt, bias, C, C16, M, N, K, ldc, ld16, mode, lengths, t);
}
static void transL(const float* in, __half* out, int K, int N, int out_ld, int k_off) {
    dim3 grid((N + 31) / 32, (K + 31) / 32);
    transpose16_kernel<<<grid, dim3(32, 8)>>>(in, out, K, N, out_ld, k_off);
}

extern "C" void kernel_launch(void* const* d_in, const int* in_sizes, int n_in,
                              void* d_out, int out_size) {
    const float* features = (const float*)d_in[0];
    const int*   captions = (const int*)d_in[1];
    const int*   lengths  = (const int*)d_in[2];
    const float* emb      = (const float*)d_in[3];
    const float* h_fc_w   = (const float*)d_in[4];
    const float* h_fc_b   = (const float*)d_in[5];
    const float* c_fc_w   = (const float*)d_in[6];
    const float* c_fc_b   = (const float*)d_in[7];
    const float* enc_w    = (const float*)d_in[8];
    const float* enc_b    = (const float*)d_in[9];
    const float* dec_w    = (const float*)d_in[10];
    const float* dec_b    = (const float*)d_in[11];
    const float* att_w    = (const float*)d_in[12];
    const float* att_b    = (const float*)d_in[13];
    const float* beta_w   = (const float*)d_in[14];
    const float* beta_b   = (const float*)d_in[15];
    const float* w_ih     = (const float*)d_in[16];
    const float* b_ih     = (const float*)d_in[17];
    const float* w_hh     = (const float*)d_in[18];
    const float* b_hh     = (const float*)d_in[19];
    const float* cls_w    = (const float*)d_in[20];
    const float* cls_b    = (const float*)d_in[21];

    float* out = (float*)d_out;
    float* y_out = out;                               // (B, T, V)
    float* a_out = out + (size_t)Bc * Tc * Vc;        // (B, T, P)

    __half *feat16, *meanf16, *h16, *hn16, *att1_16, *xin16;
    __half *hfcT, *cfcT, *encT, *dbT, *wcatT, *clsT;
    float *cst, *gates, *bcat, *dbbias;
    cudaGetSymbolAddress((void**)&feat16,  g_feat16);
    cudaGetSymbolAddress((void**)&meanf16, g_meanf16);
    cudaGetSymbolAddress((void**)&h16,     g_h16);
    cudaGetSymbolAddress((void**)&hn16,    g_hn16);
    cudaGetSymbolAddress((void**)&att1_16, g_att1_16);
    cudaGetSymbolAddress((void**)&xin16,   g_xin16);
    cudaGetSymbolAddress((void**)&hfcT,    g_hfcT);
    cudaGetSymbolAddress((void**)&cfcT,    g_cfcT);
    cudaGetSymbolAddress((void**)&encT,    g_encT);
    cudaGetSymbolAddress((void**)&dbT,     g_dbT);
    cudaGetSymbolAddress((void**)&wcatT,   g_wcatT);
    cudaGetSymbolAddress((void**)&clsT,    g_clsT);
    cudaGetSymbolAddress((void**)&cst,     g_c);
    cudaGetSymbolAddress((void**)&gates,   g_gates);
    cudaGetSymbolAddress((void**)&bcat,    g_bcat);
    cudaGetSymbolAddress((void**)&dbbias,  g_dbbias);

    // ---- prologue --------------------------------------------------------
    f32to16_kernel<<<((Bc * Pc * Dc / 2) + 255) / 256, 256>>>(features, feat16, Bc * Pc * Dc / 2);
    transL(h_fc_w, hfcT, Dc, Hc, Dc, 0);
    transL(c_fc_w, cfcT, Dc, Hc, Dc, 0);
    transL(enc_w,  encT, Dc, Ac, Dc, 0);
    transL(dec_w,  dbT, Hc, Ac, Hc, 0);               // rows 0..511
    transL(beta_w, dbT + (size_t)Ac * Hc, Hc, Dc, Hc, 0);  // rows 512..2559
    transL(w_ih,   wcatT, Dc + Ec, 4 * Hc, KCAT, 0);
    transL(w_hh,   wcatT, Hc, 4 * Hc, KCAT, Dc + Ec);
    transL(cls_w,  clsT, Hc, Vc, Hc, 0);
    bias_prep_kernel<<<(NDB + 255) / 256, 256>>>(b_ih, b_hh, dec_b, beta_b);
    mean_kernel<<<(Bc * Dc + 255) / 256, 256>>>(features);
    embed_kernel<<<(Bc * Tc * Ec + 255) / 256, 256>>>(emb, captions);

    // h0/c0 ; att1 (fp16-only output)
    gemm64(meanf16, hfcT, h_fc_b, nullptr, h16, Bc, Hc, Dc, 0, Hc, 0, nullptr, 0);
    gemm64(meanf16, cfcT, c_fc_b, cst, nullptr, Bc, Hc, Dc, Hc, 0, 0, nullptr, 0);
    gemm128(feat16, encT, enc_b, nullptr, att1_16, Bc * Pc, Ac, Dc, 0, Ac, 0, nullptr, 0);

    // ---- sequential decode -----------------------------------------------
    for (int t = 0; t < Tc; t++) {
        // att2 | gate = h @ [dec_w ; beta_w]  (mode 2 routes by column)
        gemm64(h16, dbT, dbbias, nullptr, nullptr, Bc, NDB, Hc, 0, 0, 2, nullptr, 0);
        att_softmax_kernel<<<Bc, 512>>>(att_w, att_b, lengths, t, a_out);
        awe_xin_kernel<<<(AWE_N + ECPY_N + HCPY_N + 255) / 256, 256>>>(t);
        gemm64(xin16, wcatT, bcat, gates, nullptr, Bc, 4 * Hc, KCAT, 4 * Hc, 0, 0, nullptr, 0);
        lstm_kernel<<<(Bc * Hc + 255) / 256, 256>>>(lengths, t);
        gemm64(hn16, clsT, cls_b, y_out + (size_t)t * Vc, nullptr, Bc, Vc, Hc, Tc * Vc, 0, 0, lengths, t);
    }
}

// round 10
// speedup vs baseline: 4.9678x; 1.0390x over previous
#include <cuda_runtime.h>
#include <cuda_fp16.h>
#include <math.h>
#include <stdint.h>

// Problem constants
#define Bc 128
#define Pc 196
#define Dc 2048
#define Ac 512
#define Ec 512
#define Hc 512
#define Vc 10000
#define Tc 19
#define TMAXc 20
#define KCAT 3072   // E + D + H for fused gates GEMM
#define NDB 2560    // A + D for merged dec+beta GEMM
#define VPAD2 10112 // Vc padded to multiple of 128 (B-tile overread safety)

// ---------------- scratch (device globals; no allocation allowed) ----------
__device__ __half g_feat16[(size_t)Bc * Pc * Dc];     // fp16 copy of features
__device__ __half g_meanf16[Bc * Dc];
__device__ __half g_h16[Bc * Hc];
__device__ float  g_c[Bc * Hc];
__device__ __half g_hn16[Tc][Bc * Hc];                // per-step hn (no WAR vs cls)
__device__ __half g_att1_16[(size_t)Bc * Pc * Ac];
__device__ __half g_eseq16[(size_t)Bc * Tc * Ec];
__device__ float  g_att2[Bc * Ac];
__device__ float  g_alpha[Bc * Pc];
__device__ __half g_gate16[Bc * Dc];
__device__ __half g_xin16[Bc * KCAT];
__device__ float  g_gates[2][Bc * 4 * Hc];            // split-K partials
// transposed fp16 weights (K-major B operands: Bt[n][k])
__device__ __half g_hfcT[Hc * Dc];
__device__ __half g_cfcT[Hc * Dc];
__device__ __half g_encT[Ac * Dc];
__device__ __half g_dbT[(size_t)NDB * Hc];            // [decT(512) ; betaT(2048)]
__device__ float  g_dbbias[NDB];
__device__ __half g_wcatT[(size_t)(4 * Hc) * KCAT];
__device__ __half g_clsT[(size_t)VPAD2 * Hc];         // padded tail rows (masked)
__device__ float  g_bcat[4 * Hc];

// ---------------- helpers ---------------------------------------------------
__device__ __forceinline__ uint32_t smem_u32(const void* p) {
    uint32_t a;
    asm("{ .reg .u64 t; cvta.to.shared.u64 t, %1; cvt.u32.u64 %0, t; }" : "=r"(a) : "l"(p));
    return a;
}
__device__ __forceinline__ void cp16(uint32_t dst, const void* src) {
    asm volatile("cp.async.ca.shared.global [%0], [%1], 16;" :: "r"(dst), "l"(src));
}
#define CP_COMMIT() asm volatile("cp.async.commit_group;" ::: "memory")

__device__ __forceinline__ float sigf(float x) { return 1.f / (1.f + expf(-x)); }

// ---------------- mma.sync fp16 GEMM ----------------------------------------
// C[M,N] = epi(A[M,K] @ Bt[N,K]^T + bias)      (fp16 in, fp32 accum)
// M mult of BM. K mult of 32*gridDim.z. Bt rows padded to BN tile.
// gridDim.z>1: slice z writes raw partial to C + z*M*ldc (no bias/mask/mode).
// mode: 0 = plain (bias, C/C16, rowmask), 2 = decbeta column routing.
#define ASTR 40   // smem row stride in halfs (32 data + 8 pad = 80B, conflict-free)
template<int BM, int BN>
__global__ void __launch_bounds__(256) gemm_mma(
    const __half* __restrict__ A, const __half* __restrict__ Bt,
    const float* __restrict__ bias, float* __restrict__ C, __half* __restrict__ C16,
    int M, int N, int K, int ldc, int ld16, int mode,
    const int* __restrict__ lengths, int t)
{
    constexpr int MFRAG = BM / 32;             // 16-row frags per warp (wm dim)
    constexpr int NFRAG = BN / 32;             // 8-col frags per warp (wn dim)
    __shared__ __half sA[2][BM * ASTR];
    __shared__ __half sB[2][BN * ASTR];

    const int tid = threadIdx.x;
    const int lane = tid & 31, warp = tid >> 5;
    const int wm = warp >> 2, wn = warp & 3;   // 2 x 4 warp grid
    const int row0 = blockIdx.y * BM, col0 = blockIdx.x * BN;

    const int kchunk = K / gridDim.z;
    const __half* Ab = A + (size_t)row0 * K + (size_t)blockIdx.z * kchunk;
    const __half* Bb = Bt + (size_t)col0 * K + (size_t)blockIdx.z * kchunk;
    const int nk = kchunk >> 5;

    const uint32_t sAu = smem_u32(sA);
    const uint32_t sBu = smem_u32(sB);

    float acc[MFRAG][NFRAG][4];
    #pragma unroll
    for (int i = 0; i < MFRAG; i++)
        #pragma unroll
        for (int j = 0; j < NFRAG; j++)
            #pragma unroll
            for (int e = 0; e < 4; e++) acc[i][j][e] = 0.f;

    // ldmatrix address components
    const int aRow = wm * (BM / 2) + (lane & 15);
    const int aCol = (lane >= 16) ? 8 : 0;
    const int bRow = wn * (BN / 4) + (lane & 7);
    const int bCol = ((lane & 15) >= 8) ? 8 : 0;

    // ---- prologue load stage 0 ----
    {
        #pragma unroll
        for (int l = 0; l < BM / 64; l++) {
            int c = tid + l * 256;
            int r = c >> 2, q = c & 3;
            cp16(sAu + (uint32_t)(r * ASTR + q * 8) * 2, Ab + (size_t)r * K + q * 8);
        }
        #pragma unroll
        for (int l = 0; l < BN / 64; l++) {
            int c = tid + l * 256;
            int r = c >> 2, q = c & 3;
            cp16(sBu + (uint32_t)(r * ASTR + q * 8) * 2, Bb + (size_t)r * K + q * 8);
        }
    }
    CP_COMMIT();

    for (int i = 0; i < nk; i++) {
        int buf = i & 1;
        if (i + 1 < nk) {
            int nbuf = buf ^ 1;
            int k0 = (i + 1) << 5;
            #pragma unroll
            for (int l = 0; l < BM / 64; l++) {
                int c = tid + l * 256;
                int r = c >> 2, q = c & 3;
                cp16(sAu + (uint32_t)(nbuf * BM * ASTR + r * ASTR + q * 8) * 2,
                     Ab + (size_t)r * K + k0 + q * 8);
            }
            #pragma unroll
            for (int l = 0; l < BN / 64; l++) {
                int c = tid + l * 256;
                int r = c >> 2, q = c & 3;
                cp16(sBu + (uint32_t)(nbuf * BN * ASTR + r * ASTR + q * 8) * 2,
                     Bb + (size_t)r * K + k0 + q * 8);
            }
            CP_COMMIT();
            asm volatile("cp.async.wait_group 1;" ::: "memory");
        } else {
            asm volatile("cp.async.wait_group 0;" ::: "memory");
        }
        __syncthreads();

        uint32_t baseA = sAu + (uint32_t)(buf * BM * ASTR) * 2;
        uint32_t baseB = sBu + (uint32_t)(buf * BN * ASTR) * 2;
        #pragma unroll
        for (int ks = 0; ks < 32; ks += 16) {
            uint32_t a[MFRAG][4], b[NFRAG][2];
            #pragma unroll
            for (int mf = 0; mf < MFRAG; mf++) {
                uint32_t addr = baseA + (uint32_t)((aRow + mf * 16) * ASTR + ks + aCol) * 2;
                asm volatile("ldmatrix.sync.aligned.m8n8.x4.shared.b16 {%0,%1,%2,%3}, [%4];"
                             : "=r"(a[mf][0]), "=r"(a[mf][1]), "=r"(a[mf][2]), "=r"(a[mf][3])
                             : "r"(addr));
            }
            #pragma unroll
            for (int nf = 0; nf < NFRAG; nf++) {
                uint32_t addr = baseB + (uint32_t)((bRow + nf * 8) * ASTR + ks + bCol) * 2;
                asm volatile("ldmatrix.sync.aligned.m8n8.x2.shared.b16 {%0,%1}, [%2];"
                             : "=r"(b[nf][0]), "=r"(b[nf][1]) : "r"(addr));
            }
            #pragma unroll
            for (int mf = 0; mf < MFRAG; mf++)
                #pragma unroll
                for (int nf = 0; nf < NFRAG; nf++) {
                    float* cc = acc[mf][nf];
                    asm volatile(
                        "mma.sync.aligned.m16n8k16.row.col.f32.f16.f16.f32 "
                        "{%0,%1,%2,%3}, {%4,%5,%6,%7}, {%8,%9}, {%0,%1,%2,%3};"
                        : "+f"(cc[0]), "+f"(cc[1]), "+f"(cc[2]), "+f"(cc[3])
                        : "r"(a[mf][0]), "r"(a[mf][1]), "r"(a[mf][2]), "r"(a[mf][3]),
                          "r"(b[nf][0]), "r"(b[nf][1]));
                }
        }
        __syncthreads();
    }

    // ---- epilogue ----
    const bool partial = (gridDim.z > 1);
    float* Cz = partial ? (C + (size_t)blockIdx.z * M * ldc) : C;
    const int mbase = row0 + wm * (BM / 2);
    const int nbase = col0 + wn * (BN / 4);
    #pragma unroll
    for (int mf = 0; mf < MFRAG; mf++) {
        #pragma unroll
        for (int hr = 0; hr < 2; hr++) {
            int m = mbase + mf * 16 + (lane >> 2) + hr * 8;
            float mk = 1.f;
            if (lengths) mk = (t < lengths[m] - 1) ? 1.f : 0.f;
            #pragma unroll
            for (int nf = 0; nf < NFRAG; nf++) {
                #pragma unroll
                for (int e = 0; e < 2; e++) {
                    int n = nbase + nf * 8 + (lane & 3) * 2 + e;
                    if (n < N) {
                        float v = acc[mf][nf][hr * 2 + e];
                        if (partial) {
                            Cz[(size_t)m * ldc + n] = v;
                        } else {
                            if (bias) v += bias[n];
                            if (mode == 2) {
                                if (n < Ac) g_att2[m * Ac + n] = v;
                                else g_gate16[m * Dc + (n - Ac)] = __float2half_rn(sigf(v));
                            } else {
                                v *= mk;
                                if (C)   C[(size_t)m * ldc + n] = v;
                                if (C16) C16[(size_t)m * ld16 + n] = __float2half_rn(v);
                            }
                        }
                    }
                }
            }
        }
    }
}

// ---------------- support kernels -------------------------------------------

__global__ void f32to16_kernel(const float* __restrict__ in, __half* __restrict__ out, int n2) {
    int i = blockIdx.x * blockDim.x + threadIdx.x;
    if (i < n2) {
        float2 v = ((const float2*)in)[i];
        ((__half2*)out)[i] = __floats2half2_rn(v.x, v.y);
    }
}

// in fp32 [K,N] row-major -> out fp16 [n][out_ld] at k_off
__global__ void transpose16_kernel(const float* __restrict__ in, __half* __restrict__ out,
                                   int K, int N, int out_ld, int k_off) {
    __shared__ float tile[32][33];
    int kb = blockIdx.y * 32, nb = blockIdx.x * 32;
    int x = threadIdx.x, y = threadIdx.y;   // (32, 8)
    #pragma unroll
    for (int j = 0; j < 32; j += 8) {
        int k = kb + y + j, n = nb + x;
        tile[y + j][x] = (k < K && n < N) ? in[(size_t)k * N + n] : 0.f;
    }
    __syncthreads();
    #pragma unroll
    for (int j = 0; j < 32; j += 8) {
        int n = nb + y + j, k = kb + x;
        if (n < N && k < K) out[(size_t)n * out_ld + k_off + k] = __float2half_rn(tile[x][y + j]);
    }
}

// zero-pad clsT tail rows (Vc..VPAD2) so B-tile overreads are defined
__global__ void clspad_kernel() {
    int i = blockIdx.x * blockDim.x + threadIdx.x;
    int total = (VPAD2 - Vc) * Hc;
    if (i < total) g_clsT[(size_t)Vc * Hc + i] = __float2half_rn(0.f);
}

__global__ void bias_prep_kernel(const float* __restrict__ bi, const float* __restrict__ bh,
                                 const float* __restrict__ db, const float* __restrict__ bb) {
    int i = blockIdx.x * blockDim.x + threadIdx.x;
    if (i < 4 * Hc) g_bcat[i] = bi[i] + bh[i];
    if (i < NDB) g_dbbias[i] = (i < Ac) ? db[i] : bb[i - Ac];
}

__global__ void mean_kernel(const float* __restrict__ f) {
    int idx = blockIdx.x * blockDim.x + threadIdx.x;
    if (idx >= Bc * Dc) return;
    int b = idx / Dc, d = idx % Dc;
    const float* p = f + (size_t)b * Pc * Dc + d;
    float s = 0.f;
    #pragma unroll 4
    for (int i = 0; i < Pc; i++) s += p[(size_t)i * Dc];
    g_meanf16[idx] = __float2half_rn(s * (1.0f / Pc));
}

__global__ void embed_kernel(const float* __restrict__ emb, const int* __restrict__ cap) {
    int idx = blockIdx.x * blockDim.x + threadIdx.x;
    if (idx >= Bc * Tc * Ec) return;
    int j = idx % Ec;
    int bt = idx / Ec;
    int t = bt % Tc;
    int b = bt / Tc;
    int tok = cap[b * TMAXc + t];
    g_eseq16[idx] = __float2half_rn(emb[(size_t)tok * Ec + j]);
}

// fused: e = relu(att1 + att2) @ att_w + att_b ; alpha = softmax(e) ; masked out
__global__ void __launch_bounds__(512) att_softmax_kernel(
    const float* __restrict__ att_w, const float* __restrict__ att_b,
    const int* __restrict__ lengths, int t, float* __restrict__ out_alphas)
{
    __shared__ float s2[Ac];
    __shared__ float sw[Ac];
    __shared__ float se[224];
    __shared__ float red[256];
    int b = blockIdx.x;
    int tid = threadIdx.x;   // 512
    s2[tid] = g_att2[b * Ac + tid];
    sw[tid] = att_w[tid];
    __syncthreads();

    int warp = tid >> 5, lane = tid & 31;
    float attb = att_b[0];
    for (int p = warp; p < Pc; p += 16) {
        const __half2* a1 = (const __half2*)(g_att1_16 + ((size_t)b * Pc + p) * Ac);
        float s = 0.f;
        #pragma unroll
        for (int k = 0; k < 8; k++) {
            int h2i = lane + 32 * k;
            float2 v = __half22float2(a1[h2i]);
            int a0 = 2 * h2i;
            s += fmaxf(v.x + s2[a0], 0.f) * sw[a0];
            s += fmaxf(v.y + s2[a0 + 1], 0.f) * sw[a0 + 1];
        }
        #pragma unroll
        for (int o = 16; o > 0; o >>= 1) s += __shfl_xor_sync(0xffffffffu, s, o);
        if (lane == 0) se[p] = s + attb;
    }
    __syncthreads();

    float v = (tid < Pc) ? se[tid] : -1e30f;
    if (tid < 256) red[tid] = v;
    __syncthreads();
    for (int s = 128; s > 0; s >>= 1) {
        if (tid < s) red[tid] = fmaxf(red[tid], red[tid + s]);
        __syncthreads();
    }
    float mx = red[0];
    __syncthreads();
    float ex = (tid < Pc) ? expf(v - mx) : 0.f;
    if (tid < 256) red[tid] = ex;
    __syncthreads();
    for (int s = 128; s > 0; s >>= 1) {
        if (tid < s) red[tid] += red[tid + s];
        __syncthreads();
    }
    float inv = 1.0f / red[0];
    if (tid < Pc) {
        float al = ex * inv;
        g_alpha[b * Pc + tid] = al;
        float mf = (t < lengths[b] - 1) ? 1.f : 0.f;
        out_alphas[((size_t)b * Tc + t) * Pc + tid] = al * mf;
    }
}

// fused: xin = [e_t | gate * (alpha @ features) | h]  (uint4 = 8 halfs per lane)
#define AWE8 (Bc * Dc / 8)   // 32768
#define EC8  (Bc * Ec / 8)   // 8192
#define HC8  (Bc * Hc / 8)   // 8192
__device__ __forceinline__ void h2acc(uint32_t h2, float a, float& x, float& y) {
    float2 v = __half22float2(*(__half2*)&h2);
    x += a * v.x;
    y += a * v.y;
}
__global__ void awe_xin_kernel(int t) {
    int idx = blockIdx.x * blockDim.x + threadIdx.x;
    uint4* xin4 = (uint4*)g_xin16;
    if (idx < AWE8) {
        int b = idx / (Dc / 8), d8 = idx % (Dc / 8);
        const uint4* fp = ((const uint4*)g_feat16) + (size_t)b * Pc * (Dc / 8) + d8;
        const float* al = g_alpha + b * Pc;
        float s[8] = {0.f, 0.f, 0.f, 0.f, 0.f, 0.f, 0.f, 0.f};
        #pragma unroll 2
        for (int p = 0; p < Pc; p++) {
            float a = al[p];
            uint4 v = fp[(size_t)p * (Dc / 8)];
            h2acc(v.x, a, s[0], s[1]);
            h2acc(v.y, a, s[2], s[3]);
            h2acc(v.z, a, s[4], s[5]);
            h2acc(v.w, a, s[6], s[7]);
        }
        uint4 g4 = ((const uint4*)g_gate16)[b * (Dc / 8) + d8];
        float2 g0 = __half22float2(*(__half2*)&g4.x);
        float2 g1 = __half22float2(*(__half2*)&g4.y);
        float2 g2 = __half22float2(*(__half2*)&g4.z);
        float2 g3 = __half22float2(*(__half2*)&g4.w);
        __half2 r0 = __floats2half2_rn(s[0] * g0.x, s[1] * g0.y);
        __half2 r1 = __floats2half2_rn(s[2] * g1.x, s[3] * g1.y);
        __half2 r2 = __floats2half2_rn(s[4] * g2.x, s[5] * g2.y);
        __half2 r3 = __floats2half2_rn(s[6] * g3.x, s[7] * g3.y);
        uint4 r;
        r.x = *(uint32_t*)&r0; r.y = *(uint32_t*)&r1;
        r.z = *(uint32_t*)&r2; r.w = *(uint32_t*)&r3;
        xin4[b * (KCAT / 8) + (Ec / 8) + d8] = r;
    } else if (idx < AWE8 + EC8) {
        int i = idx - AWE8;
        int b = i / (Ec / 8), j = i % (Ec / 8);
        xin4[b * (KCAT / 8) + j] =
            ((const uint4*)g_eseq16)[((size_t)b * Tc + t) * (Ec / 8) + j];
    } else if (idx < AWE8 + EC8 + HC8) {
        int i = idx - AWE8 - EC8;
        int b = i / (Hc / 8), j = i % (Hc / 8);
        xin4[b * (KCAT / 8) + ((Ec + Dc) / 8) + j] =
            ((const uint4*)g_h16)[b * (Hc / 8) + j];
    }
}

// LSTM pointwise: sums 2 gate partials + bcat bias; masked carry update
__global__ void lstm_kernel(const int* __restrict__ lengths, int t) {
    int idx = blockIdx.x * blockDim.x + threadIdx.x;
    if (idx >= Bc * Hc) return;
    int b = idx / Hc, j = idx % Hc;
    size_t base = (size_t)b * 4 * Hc;
    const float* g0 = g_gates[0] + base;
    const float* g1 = g_gates[1] + base;
    float i_ = g0[j] + g1[j] + g_bcat[j];
    float f_ = g0[Hc + j] + g1[Hc + j] + g_bcat[Hc + j];
    float gg = g0[2 * Hc + j] + g1[2 * Hc + j] + g_bcat[2 * Hc + j];
    float o_ = g0[3 * Hc + j] + g1[3 * Hc + j] + g_bcat[3 * Hc + j];
    float cn = sigf(f_) * g_c[idx] + sigf(i_) * tanhf(gg);
    float hn = sigf(o_) * tanhf(cn);
    g_hn16[t][idx] = __float2half_rn(hn);
    if (t < lengths[b] - 1) {
        g_h16[idx] = __float2half_rn(hn);
        g_c[idx] = cn;
    }
}

// ---------------- launcher ---------------------------------------------------

static void gemm64x64(const __half* A, const __half* Bt, const float* bias,
                      float* C, __half* C16, int M, int N, int K, int ldc, int ld16,
                      int mode, const int* lengths, int t, int splitk) {
    dim3 grid((N + 63) / 64, M / 64, splitk);
    gemm_mma<64, 64><<<grid, 256>>>(A, Bt, bias, C, C16, M, N, K, ldc, ld16, mode, lengths, t);
}
static void gemm64x128(const __half* A, const __half* Bt, const float* bias,
                       float* C, __half* C16, int M, int N, int K, int ldc, int ld16,
                       int mode, const int* lengths, int t, cudaStream_t st) {
    dim3 grid((N + 127) / 128, M / 64);
    gemm_mma<64, 128><<<grid, 256, 0, st>>>(A, Bt, bias, C, C16, M, N, K, ldc, ld16, mode, lengths, t);
}
static void transL(const float* in, __half* out, int K, int N, int out_ld, int k_off) {
    dim3 grid((N + 31) / 32, (K + 31) / 32);
    transpose16_kernel<<<grid, dim3(32, 8)>>>(in, out, K, N, out_ld, k_off);
}

extern "C" void kernel_launch(void* const* d_in, const int* in_sizes, int n_in,
                              void* d_out, int out_size) {
    const float* features = (const float*)d_in[0];
    const int*   captions = (const int*)d_in[1];
    const int*   lengths  = (const int*)d_in[2];
    const float* emb      = (const float*)d_in[3];
    const float* h_fc_w   = (const float*)d_in[4];
    const float* h_fc_b   = (const float*)d_in[5];
    const float* c_fc_w   = (const float*)d_in[6];
    const float* c_fc_b   = (const float*)d_in[7];
    const float* enc_w    = (const float*)d_in[8];
    const float* enc_b    = (const float*)d_in[9];
    const float* dec_w    = (const float*)d_in[10];
    const float* dec_b    = (const float*)d_in[11];
    const float* att_w    = (const float*)d_in[12];
    const float* att_b    = (const float*)d_in[13];
    const float* beta_w   = (const float*)d_in[14];
    const float* beta_b   = (const float*)d_in[15];
    const float* w_ih     = (const float*)d_in[16];
    const float* b_ih     = (const float*)d_in[17];
    const float* w_hh     = (const float*)d_in[18];
    const float* b_hh     = (const float*)d_in[19];
    const float* cls_w    = (const float*)d_in[20];
    const float* cls_b    = (const float*)d_in[21];

    float* out = (float*)d_out;
    float* y_out = out;                               // (B, T, V)
    float* a_out = out + (size_t)Bc * Tc * Vc;        // (B, T, P)

    __half *feat16, *meanf16, *h16, *hn16, *att1_16, *xin16;
    __half *hfcT, *cfcT, *encT, *dbT, *wcatT, *clsT;
    float *cst, *gates, *bcat, *dbbias;
    cudaGetSymbolAddress((void**)&feat16,  g_feat16);
    cudaGetSymbolAddress((void**)&meanf16, g_meanf16);
    cudaGetSymbolAddress((void**)&h16,     g_h16);
    cudaGetSymbolAddress((void**)&hn16,    g_hn16);
    cudaGetSymbolAddress((void**)&att1_16, g_att1_16);
    cudaGetSymbolAddress((void**)&xin16,   g_xin16);
    cudaGetSymbolAddress((void**)&hfcT,    g_hfcT);
    cudaGetSymbolAddress((void**)&cfcT,    g_cfcT);
    cudaGetSymbolAddress((void**)&encT,    g_encT);
    cudaGetSymbolAddress((void**)&dbT,     g_dbT);
    cudaGetSymbolAddress((void**)&wcatT,   g_wcatT);
    cudaGetSymbolAddress((void**)&clsT,    g_clsT);
    cudaGetSymbolAddress((void**)&cst,     g_c);
    cudaGetSymbolAddress((void**)&gates,   g_gates);
    cudaGetSymbolAddress((void**)&bcat,    g_bcat);
    cudaGetSymbolAddress((void**)&dbbias,  g_dbbias);

    // side stream + events for cls overlap (created per call; capture-safe fork/join)
    cudaStream_t s2;
    cudaStreamCreateWithFlags(&s2, cudaStreamNonBlocking);
    cudaEvent_t evFork[Tc], evJoin;
    for (int t = 0; t < Tc; t++) cudaEventCreateWithFlags(&evFork[t], cudaEventDisableTiming);
    cudaEventCreateWithFlags(&evJoin, cudaEventDisableTiming);

    // ---- prologue --------------------------------------------------------
    f32to16_kernel<<<((Bc * Pc * Dc / 2) + 255) / 256, 256>>>(features, feat16, Bc * Pc * Dc / 2);
    transL(h_fc_w, hfcT, Dc, Hc, Dc, 0);
    transL(c_fc_w, cfcT, Dc, Hc, Dc, 0);
    transL(enc_w,  encT, Dc, Ac, Dc, 0);
    transL(dec_w,  dbT, Hc, Ac, Hc, 0);               // rows 0..511
    transL(beta_w, dbT + (size_t)Ac * Hc, Hc, Dc, Hc, 0);  // rows 512..2559
    transL(w_ih,   wcatT, Dc + Ec, 4 * Hc, KCAT, 0);
    transL(w_hh,   wcatT, Hc, 4 * Hc, KCAT, Dc + Ec);
    transL(cls_w,  clsT, Hc, Vc, Hc, 0);
    clspad_kernel<<<(((VPAD2 - Vc) * Hc) + 255) / 256, 256>>>();
    bias_prep_kernel<<<(NDB + 255) / 256, 256>>>(b_ih, b_hh, dec_b, beta_b);
    mean_kernel<<<(Bc * Dc + 255) / 256, 256>>>(features);
    embed_kernel<<<(Bc * Tc * Ec + 255) / 256, 256>>>(emb, captions);

    // h0/c0 ; att1 (fp16-only output)
    gemm64x64(meanf16, hfcT, h_fc_b, nullptr, h16, Bc, Hc, Dc, 0, Hc, 0, nullptr, 0, 1);
    gemm64x64(meanf16, cfcT, c_fc_b, cst, nullptr, Bc, Hc, Dc, Hc, 0, 0, nullptr, 0, 1);
    gemm64x128(feat16, encT, enc_b, nullptr, att1_16, Bc * Pc, Ac, Dc, 0, Ac, 0, nullptr, 0, 0);

    // ---- sequential decode -----------------------------------------------
    for (int t = 0; t < Tc; t++) {
        // att2 | gate = h @ [dec_w ; beta_w]  (mode 2 routes by column)
        gemm64x64(h16, dbT, dbbias, nullptr, nullptr, Bc, NDB, Hc, 0, 0, 2, nullptr, 0, 1);
        att_softmax_kernel<<<Bc, 512>>>(att_w, att_b, lengths, t, a_out);
        awe_xin_kernel<<<(AWE8 + EC8 + HC8 + 255) / 256, 256>>>(t);
        gemm64x64(xin16, wcatT, nullptr, gates, nullptr, Bc, 4 * Hc, KCAT, 4 * Hc, 0, 0, nullptr, 0, 2);
        lstm_kernel<<<(Bc * Hc + 255) / 256, 256>>>(lengths, t);
        // fork: cls on side stream (reads only per-step hn buffer + static weights)
        cudaEventRecord(evFork[t], 0);
        cudaStreamWaitEvent(s2, evFork[t], 0);
        gemm64x128(hn16 + (size_t)t * Bc * Hc, clsT, cls_b, y_out + (size_t)t * Vc, nullptr,
                   Bc, Vc, Hc, Tc * Vc, 0, 0, lengths, t, s2);
    }
    // join side stream back into capture stream
    cudaEventRecord(evJoin, s2);
    cudaStreamWaitEvent(0, evJoin, 0);
}

// round 11
// speedup vs baseline: 6.1583x; 1.2396x over previous
#include <cuda_runtime.h>
#include <cuda_fp16.h>
#include <math.h>
#include <stdint.h>

// Problem constants
#define Bc 128
#define Pc 196
#define Dc 2048
#define Ac 512
#define Ec 512
#define Hc 512
#define Vc 10000
#define Tc 19
#define TMAXc 20
#define KCAT 3072   // E + D + H for fused gates GEMM
#define NDB 2560    // A + D for merged dec+beta GEMM
#define VPAD2 10112 // Vc padded to multiple of 128 (B-tile overread safety)
#define NSPL 4      // split-K for gates GEMM inside persistent kernel

// ---------------- scratch (device globals; no allocation allowed) ----------
__device__ __half g_feat16[(size_t)Bc * Pc * Dc];
__device__ __half g_meanf16[Bc * Dc];
__device__ __half g_h16[Bc * Hc];
__device__ float  g_c[Bc * Hc];
__device__ __half g_hn16[Tc][Bc * Hc];                // per-step hn for batched cls
__device__ __half g_att1_16[(size_t)Bc * Pc * Ac];
__device__ __half g_eseq16[(size_t)Bc * Tc * Ec];
__device__ float  g_att2[Bc * Ac];
__device__ float  g_alpha[Bc * Pc];
__device__ __half g_gate16[Bc * Dc];
__device__ __half g_xin16[Bc * KCAT];
__device__ float  g_gates[NSPL][Bc * 4 * Hc];
// transposed fp16 weights (K-major B operands: Bt[n][k])
__device__ __half g_hfcT[Hc * Dc];
__device__ __half g_cfcT[Hc * Dc];
__device__ __half g_encT[Ac * Dc];
__device__ __half g_dbT[(size_t)NDB * Hc];
__device__ float  g_dbbias[NDB];
__device__ __half g_wcatT[(size_t)(4 * Hc) * KCAT];
__device__ __half g_clsT[(size_t)VPAD2 * Hc];
__device__ float  g_bcat[4 * Hc];
// software grid barrier state
__device__ unsigned g_bar_count = 0;
__device__ unsigned g_bar_gen = 0;

// ---------------- helpers ---------------------------------------------------
__device__ __forceinline__ uint32_t smem_u32(const void* p) {
    uint32_t a;
    asm("{ .reg .u64 t; cvta.to.shared.u64 t, %1; cvt.u32.u64 %0, t; }" : "=r"(a) : "l"(p));
    return a;
}
__device__ __forceinline__ void cp16(uint32_t dst, const void* src) {
    asm volatile("cp.async.ca.shared.global [%0], [%1], 16;" :: "r"(dst), "l"(src));
}
#define CP_COMMIT() asm volatile("cp.async.commit_group;" ::: "memory")

__device__ __forceinline__ float sigf(float x) { return 1.f / (1.f + expf(-x)); }

__device__ __forceinline__ void grid_bar(unsigned nb) {
    __syncthreads();
    if (threadIdx.x == 0) {
        __threadfence();
        unsigned gen = atomicAdd(&g_bar_gen, 0u);
        unsigned prev = atomicAdd(&g_bar_count, 1u);
        if (prev == nb - 1) {
            atomicExch(&g_bar_count, 0u);
            __threadfence();
            atomicAdd(&g_bar_gen, 1u);
        } else {
            while (atomicAdd(&g_bar_gen, 0u) == gen) __nanosleep(64);
        }
        __threadfence();
    }
    __syncthreads();
}

#define ASTR 40   // smem row stride in halfs (32 data + 8 pad)
struct GemmSm { __half A[2][64 * ASTR]; __half B[2][64 * ASTR]; };   // 20480 B
struct AttSm  { float s2[Ac]; float sw[Ac]; float se[224]; float red[256]; };
union SmemU { GemmSm g; AttSm a; };

// 64x64 double-buffered mma core; all 256 threads participate.
__device__ __forceinline__ void gemm_core(SmemU& sm,
    const __half* __restrict__ Ab, const __half* __restrict__ Bb,
    int nk, int lda, int ldb, float acc[2][2][4])
{
    const int tid = threadIdx.x;
    const int lane = tid & 31, warp = tid >> 5;
    const int wm = warp >> 2, wn = warp & 3;
    const uint32_t sAu = smem_u32(sm.g.A);
    const uint32_t sBu = smem_u32(sm.g.B);
    const int aRow = wm * 32 + (lane & 15);
    const int aCol = (lane >= 16) ? 8 : 0;
    const int bRow = wn * 16 + (lane & 7);
    const int bCol = ((lane & 15) >= 8) ? 8 : 0;
    const int lr = tid >> 2, lq = tid & 3;

    #pragma unroll
    for (int i = 0; i < 2; i++)
        #pragma unroll
        for (int j = 0; j < 2; j++)
            #pragma unroll
            for (int e = 0; e < 4; e++) acc[i][j][e] = 0.f;

    cp16(sAu + (uint32_t)(lr * ASTR + lq * 8) * 2, Ab + (size_t)lr * lda + lq * 8);
    cp16(sBu + (uint32_t)(lr * ASTR + lq * 8) * 2, Bb + (size_t)lr * ldb + lq * 8);
    CP_COMMIT();

    for (int i = 0; i < nk; i++) {
        int buf = i & 1;
        if (i + 1 < nk) {
            int nbuf = buf ^ 1;
            int k0 = (i + 1) << 5;
            cp16(sAu + (uint32_t)(nbuf * 64 * ASTR + lr * ASTR + lq * 8) * 2,
                 Ab + (size_t)lr * lda + k0 + lq * 8);
            cp16(sBu + (uint32_t)(nbuf * 64 * ASTR + lr * ASTR + lq * 8) * 2,
                 Bb + (size_t)lr * ldb + k0 + lq * 8);
            CP_COMMIT();
            asm volatile("cp.async.wait_group 1;" ::: "memory");
        } else {
            asm volatile("cp.async.wait_group 0;" ::: "memory");
        }
        __syncthreads();
        uint32_t baseA = sAu + (uint32_t)(buf * 64 * ASTR) * 2;
        uint32_t baseB = sBu + (uint32_t)(buf * 64 * ASTR) * 2;
        #pragma unroll
        for (int ks = 0; ks < 32; ks += 16) {
            uint32_t a[2][4], b[2][2];
            #pragma unroll
            for (int mf = 0; mf < 2; mf++) {
                uint32_t addr = baseA + (uint32_t)((aRow + mf * 16) * ASTR + ks + aCol) * 2;
                asm volatile("ldmatrix.sync.aligned.m8n8.x4.shared.b16 {%0,%1,%2,%3}, [%4];"
                             : "=r"(a[mf][0]), "=r"(a[mf][1]), "=r"(a[mf][2]), "=r"(a[mf][3])
                             : "r"(addr));
            }
            #pragma unroll
            for (int nf = 0; nf < 2; nf++) {
                uint32_t addr = baseB + (uint32_t)((bRow + nf * 8) * ASTR + ks + bCol) * 2;
                asm volatile("ldmatrix.sync.aligned.m8n8.x2.shared.b16 {%0,%1}, [%2];"
                             : "=r"(b[nf][0]), "=r"(b[nf][1]) : "r"(addr));
            }
            #pragma unroll
            for (int mf = 0; mf < 2; mf++)
                #pragma unroll
                for (int nf = 0; nf < 2; nf++) {
                    float* cc = acc[mf][nf];
                    asm volatile(
                        "mma.sync.aligned.m16n8k16.row.col.f32.f16.f16.f32 "
                        "{%0,%1,%2,%3}, {%4,%5,%6,%7}, {%8,%9}, {%0,%1,%2,%3};"
                        : "+f"(cc[0]), "+f"(cc[1]), "+f"(cc[2]), "+f"(cc[3])
                        : "r"(a[mf][0]), "r"(a[mf][1]), "r"(a[mf][2]), "r"(a[mf][3]),
                          "r"(b[nf][0]), "r"(b[nf][1]));
                }
        }
        __syncthreads();
    }
}

// ---------------- persistent step-loop kernel --------------------------------
#define AWE8 (Bc * Dc / 8)
#define EC8  (Bc * Ec / 8)
#define HC8  (Bc * Hc / 8)
__device__ __forceinline__ void h2acc(uint32_t h2, float a, float& x, float& y) {
    float2 v = __half22float2(*(__half2*)&h2);
    x += a * v.x;
    y += a * v.y;
}

__global__ void __launch_bounds__(256, 2) step_loop_kernel(
    const float* __restrict__ att_w, const float* __restrict__ att_b,
    const int* __restrict__ lengths, float* __restrict__ a_out)
{
    __shared__ SmemU sm;
    const int tid = threadIdx.x;
    const int lane = tid & 31, warp = tid >> 5;
    const int wm = warp >> 2, wn = warp & 3;
    const unsigned nb = gridDim.x;
    const int gsize = (int)nb * 256;
    const int gid = blockIdx.x * 256 + tid;

    for (int t = 0; t < Tc; t++) {
        // ---- Phase A: [att2 | gate] = h @ dbT + dbbias (mode-2 routing) ----
        for (int u = blockIdx.x; u < 80; u += (int)nb) {
            int row0 = (u / 40) * 64, col0 = (u % 40) * 64;
            float acc[2][2][4];
            gemm_core(sm, g_h16 + (size_t)row0 * Hc, g_dbT + (size_t)col0 * Hc,
                      Hc >> 5, Hc, Hc, acc);
            int mbase = row0 + wm * 32, nbase = col0 + wn * 16;
            #pragma unroll
            for (int mf = 0; mf < 2; mf++)
                #pragma unroll
                for (int hr = 0; hr < 2; hr++) {
                    int m = mbase + mf * 16 + (lane >> 2) + hr * 8;
                    #pragma unroll
                    for (int nf = 0; nf < 2; nf++)
                        #pragma unroll
                        for (int e = 0; e < 2; e++) {
                            int n = nbase + nf * 8 + (lane & 3) * 2 + e;
                            float v = acc[mf][nf][hr * 2 + e] + g_dbbias[n];
                            if (n < Ac) g_att2[m * Ac + n] = v;
                            else g_gate16[m * Dc + (n - Ac)] = __float2half_rn(sigf(v));
                        }
                }
        }
        grid_bar(nb);

        // ---- Phase B: e = relu(att1 + att2) @ att_w + att_b; softmax ----
        for (int b = blockIdx.x; b < Bc; b += (int)nb) {
            for (int i = tid; i < Ac; i += 256) {
                sm.a.s2[i] = g_att2[b * Ac + i];
                sm.a.sw[i] = att_w[i];
            }
            __syncthreads();
            float attb = att_b[0];
            for (int p = warp; p < Pc; p += 8) {
                const __half2* a1 = (const __half2*)(g_att1_16 + ((size_t)b * Pc + p) * Ac);
                float s = 0.f;
                #pragma unroll
                for (int k = 0; k < 8; k++) {
                    int h2i = lane + 32 * k;
                    float2 v = __half22float2(a1[h2i]);
                    int a0 = 2 * h2i;
                    s += fmaxf(v.x + sm.a.s2[a0], 0.f) * sm.a.sw[a0];
                    s += fmaxf(v.y + sm.a.s2[a0 + 1], 0.f) * sm.a.sw[a0 + 1];
                }
                #pragma unroll
                for (int o = 16; o > 0; o >>= 1) s += __shfl_xor_sync(0xffffffffu, s, o);
                if (lane == 0) sm.a.se[p] = s + attb;
            }
            __syncthreads();
            float v = (tid < Pc) ? sm.a.se[tid] : -1e30f;
            sm.a.red[tid] = v;
            __syncthreads();
            for (int s = 128; s > 0; s >>= 1) {
                if (tid < s) sm.a.red[tid] = fmaxf(sm.a.red[tid], sm.a.red[tid + s]);
                __syncthreads();
            }
            float mx = sm.a.red[0];
            __syncthreads();
            float ex = (tid < Pc) ? expf(v - mx) : 0.f;
            sm.a.red[tid] = ex;
            __syncthreads();
            for (int s = 128; s > 0; s >>= 1) {
                if (tid < s) sm.a.red[tid] += sm.a.red[tid + s];
                __syncthreads();
            }
            float inv = 1.0f / sm.a.red[0];
            if (tid < Pc) {
                float al = ex * inv;
                g_alpha[b * Pc + tid] = al;
                float mf = (t < lengths[b] - 1) ? 1.f : 0.f;
                a_out[((size_t)b * Tc + t) * Pc + tid] = al * mf;
            }
            __syncthreads();
        }
        grid_bar(nb);

        // ---- Phase C: xin = [e_t | gate * (alpha @ features) | h] ----
        for (int idx = gid; idx < AWE8 + EC8 + HC8; idx += gsize) {
            uint4* xin4 = (uint4*)g_xin16;
            if (idx < AWE8) {
                int b = idx / (Dc / 8), d8 = idx % (Dc / 8);
                const uint4* fp = ((const uint4*)g_feat16) + (size_t)b * Pc * (Dc / 8) + d8;
                const float* al = g_alpha + b * Pc;
                float s[8] = {0.f, 0.f, 0.f, 0.f, 0.f, 0.f, 0.f, 0.f};
                #pragma unroll 4
                for (int p = 0; p < Pc; p++) {
                    float a = al[p];
                    uint4 v = fp[(size_t)p * (Dc / 8)];
                    h2acc(v.x, a, s[0], s[1]);
                    h2acc(v.y, a, s[2], s[3]);
                    h2acc(v.z, a, s[4], s[5]);
                    h2acc(v.w, a, s[6], s[7]);
                }
                uint4 g4 = ((const uint4*)g_gate16)[b * (Dc / 8) + d8];
                float2 g0 = __half22float2(*(__half2*)&g4.x);
                float2 g1 = __half22float2(*(__half2*)&g4.y);
                float2 g2 = __half22float2(*(__half2*)&g4.z);
                float2 g3 = __half22float2(*(__half2*)&g4.w);
                __half2 r0 = __floats2half2_rn(s[0] * g0.x, s[1] * g0.y);
                __half2 r1 = __floats2half2_rn(s[2] * g1.x, s[3] * g1.y);
                __half2 r2 = __floats2half2_rn(s[4] * g2.x, s[5] * g2.y);
                __half2 r3 = __floats2half2_rn(s[6] * g3.x, s[7] * g3.y);
                uint4 r;
                r.x = *(uint32_t*)&r0; r.y = *(uint32_t*)&r1;
                r.z = *(uint32_t*)&r2; r.w = *(uint32_t*)&r3;
                xin4[b * (KCAT / 8) + (Ec / 8) + d8] = r;
            } else if (idx < AWE8 + EC8) {
                int i = idx - AWE8;
                int b = i / (Ec / 8), j = i % (Ec / 8);
                xin4[b * (KCAT / 8) + j] =
                    ((const uint4*)g_eseq16)[((size_t)b * Tc + t) * (Ec / 8) + j];
            } else {
                int i = idx - AWE8 - EC8;
                int b = i / (Hc / 8), j = i % (Hc / 8);
                xin4[b * (KCAT / 8) + ((Ec + Dc) / 8) + j] =
                    ((const uint4*)g_h16)[b * (Hc / 8) + j];
            }
        }
        grid_bar(nb);

        // ---- Phase D: gates partials = xin @ wcatT (split-K=4) ----
        for (int u = blockIdx.x; u < 2 * 32 * NSPL; u += (int)nb) {
            int z = u & (NSPL - 1), uu = u >> 2;
            int row0 = (uu / 32) * 64, col0 = (uu % 32) * 64;
            float acc[2][2][4];
            gemm_core(sm, g_xin16 + (size_t)row0 * KCAT + z * (KCAT / NSPL),
                      g_wcatT + (size_t)col0 * KCAT + z * (KCAT / NSPL),
                      (KCAT / NSPL) >> 5, KCAT, KCAT, acc);
            int mbase = row0 + wm * 32, nbase = col0 + wn * 16;
            float* gz = g_gates[z];
            #pragma unroll
            for (int mf = 0; mf < 2; mf++)
                #pragma unroll
                for (int hr = 0; hr < 2; hr++) {
                    int m = mbase + mf * 16 + (lane >> 2) + hr * 8;
                    #pragma unroll
                    for (int nf = 0; nf < 2; nf++)
                        #pragma unroll
                        for (int e = 0; e < 2; e++) {
                            int n = nbase + nf * 8 + (lane & 3) * 2 + e;
                            gz[(size_t)m * (4 * Hc) + n] = acc[mf][nf][hr * 2 + e];
                        }
                }
        }
        grid_bar(nb);

        // ---- Phase E: LSTM pointwise ----
        for (int idx = gid; idx < Bc * Hc; idx += gsize) {
            int b = idx / Hc, j = idx % Hc;
            size_t base = (size_t)b * 4 * Hc;
            float i_ = g_bcat[j],          f_ = g_bcat[Hc + j];
            float gg = g_bcat[2 * Hc + j], o_ = g_bcat[3 * Hc + j];
            #pragma unroll
            for (int z = 0; z < NSPL; z++) {
                const float* gr = g_gates[z] + base;
                i_ += gr[j];
                f_ += gr[Hc + j];
                gg += gr[2 * Hc + j];
                o_ += gr[3 * Hc + j];
            }
            float cn = sigf(f_) * g_c[idx] + sigf(i_) * tanhf(gg);
            float hn = sigf(o_) * tanhf(cn);
            g_hn16[t][idx] = __float2half_rn(hn);
            if (t < lengths[b] - 1) {
                g_h16[idx] = __float2half_rn(hn);
                g_c[idx] = cn;
            }
        }
        grid_bar(nb);
    }
}

// ---------------- template GEMM for prologue + batched cls -------------------
// mode 0: plain bias (+C/C16). mode 3: batched cls (row m -> t=m>>7, b=m&127).
template<int BM, int BN>
__global__ void __launch_bounds__(256) gemm_mma(
    const __half* __restrict__ A, const __half* __restrict__ Bt,
    const float* __restrict__ bias, float* __restrict__ C, __half* __restrict__ C16,
    int M, int N, int K, int ldc, int ld16, int mode,
    const int* __restrict__ lengths)
{
    constexpr int MFRAG = BM / 32;
    constexpr int NFRAG = BN / 32;
    __shared__ __half sA[2][BM * ASTR];
    __shared__ __half sB[2][BN * ASTR];

    const int tid = threadIdx.x;
    const int lane = tid & 31, warp = tid >> 5;
    const int wm = warp >> 2, wn = warp & 3;
    const int row0 = blockIdx.y * BM, col0 = blockIdx.x * BN;

    const __half* Ab = A + (size_t)row0 * K;
    const __half* Bb = Bt + (size_t)col0 * K;
    const int nk = K >> 5;

    const uint32_t sAu = smem_u32(sA);
    const uint32_t sBu = smem_u32(sB);

    float acc[MFRAG][NFRAG][4];
    #pragma unroll
    for (int i = 0; i < MFRAG; i++)
        #pragma unroll
        for (int j = 0; j < NFRAG; j++)
            #pragma unroll
            for (int e = 0; e < 4; e++) acc[i][j][e] = 0.f;

    const int aRow = wm * (BM / 2) + (lane & 15);
    const int aCol = (lane >= 16) ? 8 : 0;
    const int bRow = wn * (BN / 4) + (lane & 7);
    const int bCol = ((lane & 15) >= 8) ? 8 : 0;

    {
        #pragma unroll
        for (int l = 0; l < BM / 64; l++) {
            int c = tid + l * 256;
            int r = c >> 2, q = c & 3;
            cp16(sAu + (uint32_t)(r * ASTR + q * 8) * 2, Ab + (size_t)r * K + q * 8);
        }
        #pragma unroll
        for (int l = 0; l < BN / 64; l++) {
            int c = tid + l * 256;
            int r = c >> 2, q = c & 3;
            cp16(sBu + (uint32_t)(r * ASTR + q * 8) * 2, Bb + (size_t)r * K + q * 8);
        }
    }
    CP_COMMIT();

    for (int i = 0; i < nk; i++) {
        int buf = i & 1;
        if (i + 1 < nk) {
            int nbuf = buf ^ 1;
            int k0 = (i + 1) << 5;
            #pragma unroll
            for (int l = 0; l < BM / 64; l++) {
                int c = tid + l * 256;
                int r = c >> 2, q = c & 3;
                cp16(sAu + (uint32_t)(nbuf * BM * ASTR + r * ASTR + q * 8) * 2,
                     Ab + (size_t)r * K + k0 + q * 8);
            }
            #pragma unroll
            for (int l = 0; l < BN / 64; l++) {
                int c = tid + l * 256;
                int r = c >> 2, q = c & 3;
                cp16(sBu + (uint32_t)(nbuf * BN * ASTR + r * ASTR + q * 8) * 2,
                     Bb + (size_t)r * K + k0 + q * 8);
            }
            CP_COMMIT();
            asm volatile("cp.async.wait_group 1;" ::: "memory");
        } else {
            asm volatile("cp.async.wait_group 0;" ::: "memory");
        }
        __syncthreads();

        uint32_t baseA = sAu + (uint32_t)(buf * BM * ASTR) * 2;
        uint32_t baseB = sBu + (uint32_t)(buf * BN * ASTR) * 2;
        #pragma unroll
        for (int ks = 0; ks < 32; ks += 16) {
            uint32_t a[MFRAG][4], b[NFRAG][2];
            #pragma unroll
            for (int mf = 0; mf < MFRAG; mf++) {
                uint32_t addr = baseA + (uint32_t)((aRow + mf * 16) * ASTR + ks + aCol) * 2;
                asm volatile("ldmatrix.sync.aligned.m8n8.x4.shared.b16 {%0,%1,%2,%3}, [%4];"
                             : "=r"(a[mf][0]), "=r"(a[mf][1]), "=r"(a[mf][2]), "=r"(a[mf][3])
                             : "r"(addr));
            }
            #pragma unroll
            for (int nf = 0; nf < NFRAG; nf++) {
                uint32_t addr = baseB + (uint32_t)((bRow + nf * 8) * ASTR + ks + bCol) * 2;
                asm volatile("ldmatrix.sync.aligned.m8n8.x2.shared.b16 {%0,%1}, [%2];"
                             : "=r"(b[nf][0]), "=r"(b[nf][1]) : "r"(addr));
            }
            #pragma unroll
            for (int mf = 0; mf < MFRAG; mf++)
                #pragma unroll
                for (int nf = 0; nf < NFRAG; nf++) {
                    float* cc = acc[mf][nf];
                    asm volatile(
                        "mma.sync.aligned.m16n8k16.row.col.f32.f16.f16.f32 "
                        "{%0,%1,%2,%3}, {%4,%5,%6,%7}, {%8,%9}, {%0,%1,%2,%3};"
                        : "+f"(cc[0]), "+f"(cc[1]), "+f"(cc[2]), "+f"(cc[3])
                        : "r"(a[mf][0]), "r"(a[mf][1]), "r"(a[mf][2]), "r"(a[mf][3]),
                          "r"(b[nf][0]), "r"(b[nf][1]));
                }
        }
        __syncthreads();
    }

    const int mbase = row0 + wm * (BM / 2);
    const int nbase = col0 + wn * (BN / 4);
    #pragma unroll
    for (int mf = 0; mf < MFRAG; mf++) {
        #pragma unroll
        for (int hr = 0; hr < 2; hr++) {
            int m = mbase + mf * 16 + (lane >> 2) + hr * 8;
            #pragma unroll
            for (int nf = 0; nf < NFRAG; nf++) {
                #pragma unroll
                for (int e = 0; e < 2; e++) {
                    int n = nbase + nf * 8 + (lane & 3) * 2 + e;
                    if (n < N) {
                        float v = acc[mf][nf][hr * 2 + e];
                        if (bias) v += bias[n];
                        if (mode == 3) {
                            int tt = m >> 7, bb = m & 127;
                            float mk = (tt < lengths[bb] - 1) ? 1.f : 0.f;
                            C[((size_t)bb * Tc + tt) * Vc + n] = v * mk;
                        } else {
                            if (C)   C[(size_t)m * ldc + n] = v;
                            if (C16) C16[(size_t)m * ld16 + n] = __float2half_rn(v);
                        }
                    }
                }
            }
        }
    }
}

// ---------------- support kernels -------------------------------------------

__global__ void f32to16_kernel(const float* __restrict__ in, __half* __restrict__ out, int n2) {
    int i = blockIdx.x * blockDim.x + threadIdx.x;
    if (i < n2) {
        float2 v = ((const float2*)in)[i];
        ((__half2*)out)[i] = __floats2half2_rn(v.x, v.y);
    }
}

__global__ void transpose16_kernel(const float* __restrict__ in, __half* __restrict__ out,
                                   int K, int N, int out_ld, int k_off) {
    __shared__ float tile[32][33];
    int kb = blockIdx.y * 32, nb = blockIdx.x * 32;
    int x = threadIdx.x, y = threadIdx.y;
    #pragma unroll
    for (int j = 0; j < 32; j += 8) {
        int k = kb + y + j, n = nb + x;
        tile[y + j][x] = (k < K && n < N) ? in[(size_t)k * N + n] : 0.f;
    }
    __syncthreads();
    #pragma unroll
    for (int j = 0; j < 32; j += 8) {
        int n = nb + y + j, k = kb + x;
        if (n < N && k < K) out[(size_t)n * out_ld + k_off + k] = __float2half_rn(tile[x][y + j]);
    }
}

__global__ void clspad_kernel() {
    int i = blockIdx.x * blockDim.x + threadIdx.x;
    int total = (VPAD2 - Vc) * Hc;
    if (i < total) g_clsT[(size_t)Vc * Hc + i] = __float2half_rn(0.f);
}

__global__ void bias_prep_kernel(const float* __restrict__ bi, const float* __restrict__ bh,
                                 const float* __restrict__ db, const float* __restrict__ bb) {
    int i = blockIdx.x * blockDim.x + threadIdx.x;
    if (i < 4 * Hc) g_bcat[i] = bi[i] + bh[i];
    if (i < NDB) g_dbbias[i] = (i < Ac) ? db[i] : bb[i - Ac];
}

__global__ void mean_kernel(const float* __restrict__ f) {
    int idx = blockIdx.x * blockDim.x + threadIdx.x;
    if (idx >= Bc * Dc) return;
    int b = idx / Dc, d = idx % Dc;
    const float* p = f + (size_t)b * Pc * Dc + d;
    float s = 0.f;
    #pragma unroll 4
    for (int i = 0; i < Pc; i++) s += p[(size_t)i * Dc];
    g_meanf16[idx] = __float2half_rn(s * (1.0f / Pc));
}

__global__ void embed_kernel(const float* __restrict__ emb, const int* __restrict__ cap) {
    int idx = blockIdx.x * blockDim.x + threadIdx.x;
    if (idx >= Bc * Tc * Ec) return;
    int j = idx % Ec;
    int bt = idx / Ec;
    int t = bt % Tc;
    int b = bt / Tc;
    int tok = cap[b * TMAXc + t];
    g_eseq16[idx] = __float2half_rn(emb[(size_t)tok * Ec + j]);
}

// ---------------- launcher ---------------------------------------------------

static void transL(const float* in, __half* out, int K, int N, int out_ld, int k_off) {
    dim3 grid((N + 31) / 32, (K + 31) / 32);
    transpose16_kernel<<<grid, dim3(32, 8)>>>(in, out, K, N, out_ld, k_off);
}

extern "C" void kernel_launch(void* const* d_in, const int* in_sizes, int n_in,
                              void* d_out, int out_size) {
    const float* features = (const float*)d_in[0];
    const int*   captions = (const int*)d_in[1];
    const int*   lengths  = (const int*)d_in[2];
    const float* emb      = (const float*)d_in[3];
    const float* h_fc_w   = (const float*)d_in[4];
    const float* h_fc_b   = (const float*)d_in[5];
    const float* c_fc_w   = (const float*)d_in[6];
    const float* c_fc_b   = (const float*)d_in[7];
    const float* enc_w    = (const float*)d_in[8];
    const float* enc_b    = (const float*)d_in[9];
    const float* dec_w    = (const float*)d_in[10];
    const float* dec_b    = (const float*)d_in[11];
    const float* att_w    = (const float*)d_in[12];
    const float* att_b    = (const float*)d_in[13];
    const float* beta_w   = (const float*)d_in[14];
    const float* beta_b   = (const float*)d_in[15];
    const float* w_ih     = (const float*)d_in[16];
    const float* b_ih     = (const float*)d_in[17];
    const float* w_hh     = (const float*)d_in[18];
    const float* b_hh     = (const float*)d_in[19];
    const float* cls_w    = (const float*)d_in[20];
    const float* cls_b    = (const float*)d_in[21];

    float* out = (float*)d_out;
    float* y_out = out;                               // (B, T, V)
    float* a_out = out + (size_t)Bc * Tc * Vc;        // (B, T, P)

    __half *feat16, *meanf16, *h16, *hn16, *att1_16;
    __half *hfcT, *cfcT, *encT, *dbT, *wcatT, *clsT;
    float *cst;
    cudaGetSymbolAddress((void**)&feat16,  g_feat16);
    cudaGetSymbolAddress((void**)&meanf16, g_meanf16);
    cudaGetSymbolAddress((void**)&h16,     g_h16);
    cudaGetSymbolAddress((void**)&hn16,    g_hn16);
    cudaGetSymbolAddress((void**)&att1_16, g_att1_16);
    cudaGetSymbolAddress((void**)&hfcT,    g_hfcT);
    cudaGetSymbolAddress((void**)&cfcT,    g_cfcT);
    cudaGetSymbolAddress((void**)&encT,    g_encT);
    cudaGetSymbolAddress((void**)&dbT,     g_dbT);
    cudaGetSymbolAddress((void**)&wcatT,   g_wcatT);
    cudaGetSymbolAddress((void**)&clsT,    g_clsT);
    cudaGetSymbolAddress((void**)&cst,     g_c);

    // persistent-kernel grid: guaranteed-resident block count
    int smcount = 0, occ = 0;
    cudaDeviceGetAttribute(&smcount, cudaDevAttrMultiProcessorCount, 0);
    cudaOccupancyMaxActiveBlocksPerMultiprocessor(&occ, step_loop_kernel, 256, 0);
    if (occ < 1) occ = 1;
    if (occ > 2) occ = 2;
    int nb = smcount * occ;

    // ---- prologue --------------------------------------------------------
    f32to16_kernel<<<((Bc * Pc * Dc / 2) + 255) / 256, 256>>>(features, feat16, Bc * Pc * Dc / 2);
    transL(h_fc_w, hfcT, Dc, Hc, Dc, 0);
    transL(c_fc_w, cfcT, Dc, Hc, Dc, 0);
    transL(enc_w,  encT, Dc, Ac, Dc, 0);
    transL(dec_w,  dbT, Hc, Ac, Hc, 0);
    transL(beta_w, dbT + (size_t)Ac * Hc, Hc, Dc, Hc, 0);
    transL(w_ih,   wcatT, Dc + Ec, 4 * Hc, KCAT, 0);
    transL(w_hh,   wcatT, Hc, 4 * Hc, KCAT, Dc + Ec);
    transL(cls_w,  clsT, Hc, Vc, Hc, 0);
    clspad_kernel<<<(((VPAD2 - Vc) * Hc) + 255) / 256, 256>>>();
    bias_prep_kernel<<<(NDB + 255) / 256, 256>>>(b_ih, b_hh, dec_b, beta_b);
    mean_kernel<<<(Bc * Dc + 255) / 256, 256>>>(features);
    embed_kernel<<<(Bc * Tc * Ec + 255) / 256, 256>>>(emb, captions);

    // h0 / c0 / att1
    {
        dim3 g1(Hc / 64, Bc / 64);
        gemm_mma<64, 64><<<g1, 256>>>(meanf16, hfcT, h_fc_b, nullptr, h16, Bc, Hc, Dc, 0, Hc, 0, nullptr);
        gemm_mma<64, 64><<<g1, 256>>>(meanf16, cfcT, c_fc_b, cst, nullptr, Bc, Hc, Dc, Hc, 0, 0, nullptr);
        dim3 g2(Ac / 128, (Bc * Pc) / 64);
        gemm_mma<64, 128><<<g2, 256>>>(feat16, encT, enc_b, nullptr, att1_16, Bc * Pc, Ac, Dc, 0, Ac, 0, nullptr);
    }

    // ---- persistent 19-step loop -----------------------------------------
    step_loop_kernel<<<nb, 256>>>(att_w, att_b, lengths, a_out);

    // ---- batched cls over all steps: (Tc*Bc, Vc) = hn_all @ clsT ---------
    {
        dim3 g3((Vc + 127) / 128, (Tc * Bc) / 64);
        gemm_mma<64, 128><<<g3, 256>>>(hn16, clsT, cls_b, y_out, nullptr,
                                       Tc * Bc, Vc, Hc, 0, 0, 3, lengths);
    }
}